// round 4
// baseline (speedup 1.0000x reference)
#include <cuda_runtime.h>
#include <math.h>
#include <float.h>
#include <stdint.h>

#define T_TOKENS 16384
#define HDIM     2048
#define NEXP     256
#define TOPK     8
#define TOPKG    4

#define TAU_E 3e-5f
#define TAU_G 6e-5f

// ---------------- static device scratch ----------------
__device__ float g_scores[(size_t)T_TOKENS * NEXP];                  // 16 MB
__device__ float g_Ahi[(size_t)(T_TOKENS / 16) * (HDIM / 8) * 128];  // 134 MB
__device__ float g_Alo[(size_t)(T_TOKENS / 16) * (HDIM / 8) * 128];  // 134 MB
__device__ float g_Bhi[(size_t)(NEXP / 8) * (HDIM / 8) * 64];        // 2 MB
__device__ float g_Blo[(size_t)(NEXP / 8) * (HDIM / 8) * 64];        // 2 MB
__device__ int   g_nflag;
__device__ int   g_flaglist[T_TOKENS];

// ---------------- helpers ----------------
__device__ __forceinline__ uint32_t smem_u32(const void* p) {
    uint32_t a;
    asm("{ .reg .u64 t; cvta.to.shared.u64 t, %1; cvt.u32.u64 %0, t; }" : "=r"(a) : "l"(p));
    return a;
}
__device__ __forceinline__ float tf32_rna(float v) {
    uint32_t r; asm("cvt.rna.tf32.f32 %0, %1;" : "=r"(r) : "f"(v));
    return __uint_as_float(r);
}
#define MBAR_INIT(a, n) \
    asm volatile("mbarrier.init.shared.b64 [%0], %1;" :: "r"(a), "r"((uint32_t)(n)) : "memory")
#define MBAR_EXPECT_TX(a, b) \
    asm volatile("mbarrier.arrive.expect_tx.shared.b64 _, [%0], %1;" :: "r"(a), "r"((uint32_t)(b)) : "memory")
#define MBAR_WAIT(a, ph) do {                                                   \
    uint32_t _m = (a); uint32_t _p = (ph); uint32_t _d;                         \
    asm volatile("{\n .reg .pred p;\n"                                          \
        " mbarrier.try_wait.parity.acquire.cta.shared::cta.b64 p, [%1], %2;\n"  \
        " selp.b32 %0, 1, 0, p;\n}" : "=r"(_d) : "r"(_m), "r"(_p) : "memory");  \
    if (!_d) {                                                                  \
        asm volatile("{\n .reg .pred P1;\n"                                     \
            "W_%=:\n"                                                           \
            " mbarrier.try_wait.parity.acquire.cta.shared::cta.b64 P1, [%0], %1, 0x989680;\n" \
            " @P1 bra.uni D_%=;\n bra.uni W_%=;\n"                              \
            "D_%=:\n}" :: "r"(_m), "r"(_p) : "memory");                         \
    } } while (0)

__device__ __forceinline__ void bulk_g2s(uint32_t dst, const void* src, uint32_t bytes, uint32_t mbar) {
    asm volatile(
        "cp.async.bulk.shared::cluster.global.mbarrier::complete_tx::bytes [%0], [%1], %2, [%3];"
        :: "r"(dst), "l"(src), "r"(bytes), "r"(mbar) : "memory");
}
__device__ __forceinline__ void mma_tf32(float& c0, float& c1, float& c2, float& c3,
                                         uint32_t a0, uint32_t a1, uint32_t a2, uint32_t a3,
                                         uint32_t b0, uint32_t b1) {
    asm volatile(
        "mma.sync.aligned.m16n8k8.row.col.f32.tf32.tf32.f32 "
        "{%0,%1,%2,%3}, {%4,%5,%6,%7}, {%8,%9}, {%0,%1,%2,%3};"
        : "+f"(c0), "+f"(c1), "+f"(c2), "+f"(c3)
        : "r"(a0), "r"(a1), "r"(a2), "r"(a3), "r"(b0), "r"(b1));
}
#define LDS128(r0, r1, r2, r3, a) \
    asm volatile("ld.shared.v4.b32 {%0,%1,%2,%3}, [%4];" : "=r"(r0), "=r"(r1), "=r"(r2), "=r"(r3) : "r"(a))
#define LDS64(r0, r1, a) \
    asm volatile("ld.shared.v2.b32 {%0,%1}, [%2];" : "=r"(r0), "=r"(r1) : "r"(a))

// ---------------------------------------------------------------------------
// Split kernels: Dekker split into fragment-ordered tiles.
// ---------------------------------------------------------------------------
__global__ __launch_bounds__(256) void split_a_kernel(const float* __restrict__ x) {
    int tile = blockIdx.x * 8 + (threadIdx.x >> 5);   // mt*256 + kt
    int lane = threadIdx.x & 31;
    int mt = tile >> 8;
    int kt = tile & 255;
    int gp = lane >> 2, tg = lane & 3;
    const float* xs = x + (size_t)(mt * 16) * HDIM + kt * 8;
    float v0 = __ldg(xs + gp * HDIM + tg);
    float v1 = __ldg(xs + (gp + 8) * HDIM + tg);
    float v2 = __ldg(xs + gp * HDIM + tg + 4);
    float v3 = __ldg(xs + (gp + 8) * HDIM + tg + 4);
    float h0 = tf32_rna(v0), h1 = tf32_rna(v1), h2 = tf32_rna(v2), h3 = tf32_rna(v3);
    float l0 = tf32_rna(v0 - h0), l1 = tf32_rna(v1 - h1);
    float l2 = tf32_rna(v2 - h2), l3 = tf32_rna(v3 - h3);
    size_t o = (size_t)tile * 128 + lane * 4;
    *(float4*)(g_Ahi + o) = make_float4(h0, h1, h2, h3);
    *(float4*)(g_Alo + o) = make_float4(l0, l1, l2, l3);
}

__global__ __launch_bounds__(256) void split_b_kernel(const float* __restrict__ w) {
    if (blockIdx.x == 0 && threadIdx.x == 0) g_nflag = 0;   // reset flag counter
    int tile = blockIdx.x * 8 + (threadIdx.x >> 5);   // nt*256 + kt
    int lane = threadIdx.x & 31;
    int nt = tile >> 8;
    int kt = tile & 255;
    int nn = lane >> 2, kk = lane & 3;
    const float* ws = w + (size_t)(nt * 8 + nn) * HDIM + kt * 8;
    float v0 = __ldg(ws + kk);
    float v1 = __ldg(ws + kk + 4);
    float h0 = tf32_rna(v0), h1 = tf32_rna(v1);
    float l0 = tf32_rna(v0 - h0), l1 = tf32_rna(v1 - h1);
    size_t o = (size_t)tile * 64 + lane * 2;
    g_Bhi[o] = h0; g_Bhi[o + 1] = h1;
    g_Blo[o] = l0; g_Blo[o + 1] = l1;
}

// ---------------------------------------------------------------------------
// GEMM: 3xTF32 mma.sync, BM=128 BN=256(all experts) BK=32, 2-stage bulk pipeline
// stage: Ahi 16K | Alo 16K | Bhi 32K | Blo 32K = 96 KB
// ---------------------------------------------------------------------------
#define STAGES   2
#define STG_SZ   98304
#define OFF_AH   0
#define OFF_AL   16384
#define OFF_BH   32768
#define OFF_BL   65536
#define OFF_MBAR (STAGES * STG_SZ)
#define SMEM_SZ  (OFF_MBAR + 64)
#define NITER    (HDIM / 32)   // 64

__device__ __forceinline__ void issue_stage(uint32_t sb, int s, int mt0, int kt0) {
    uint32_t stg = sb + s * STG_SZ;
    uint32_t mb  = sb + OFF_MBAR + s * 8;
    MBAR_EXPECT_TX(mb, STG_SZ);
    #pragma unroll
    for (int i = 0; i < 8; i++) {
        size_t src = ((size_t)(mt0 + i) * 256 + kt0) * 128;
        bulk_g2s(stg + OFF_AH + i * 2048, g_Ahi + src, 2048, mb);
        bulk_g2s(stg + OFF_AL + i * 2048, g_Alo + src, 2048, mb);
    }
    #pragma unroll
    for (int j = 0; j < 32; j++) {
        size_t src = ((size_t)j * 256 + kt0) * 64;
        bulk_g2s(stg + OFF_BH + j * 1024, g_Bhi + src, 1024, mb);
        bulk_g2s(stg + OFF_BL + j * 1024, g_Blo + src, 1024, mb);
    }
}

__global__ __launch_bounds__(256, 1) void gemm_mma_kernel() {
    extern __shared__ __align__(1024) char smem[];
    const uint32_t sb = smem_u32(smem);
    const int tid  = threadIdx.x;
    const int wid  = tid >> 5;
    const int lane = tid & 31;
    const int wm   = wid >> 2;          // 0..1 (64 rows each)
    const int wn   = wid & 3;           // 0..3 (64 cols each)
    const int mt0  = blockIdx.x * 8;    // 8 m-tiles / CTA

    if (tid == 0) {
        #pragma unroll
        for (int s = 0; s < STAGES; s++) MBAR_INIT(sb + OFF_MBAR + s * 8, 1);
    }
    __syncthreads();
    if (tid == 0) {
        issue_stage(sb, 0, mt0, 0);
        issue_stage(sb, 1, mt0, 4);
    }

    float acc[4][8][4];
    #pragma unroll
    for (int i = 0; i < 4; i++)
        #pragma unroll
        for (int j = 0; j < 8; j++)
            #pragma unroll
            for (int q = 0; q < 4; q++) acc[i][j][q] = 0.0f;

    int ph[STAGES] = {0, 0};

    for (int it = 0; it < NITER; it++) {
        const int s = it & 1;
        const uint32_t stg = sb + s * STG_SZ;
        MBAR_WAIT(sb + OFF_MBAR + s * 8, ph[s]);
        ph[s] ^= 1;

        #pragma unroll
        for (int ktl = 0; ktl < 4; ktl++) {
            uint32_t ah[4][4], al[4][4], bh[8][2], bl[8][2];
            #pragma unroll
            for (int mi = 0; mi < 4; mi++) {
                uint32_t off = (uint32_t)(((wm * 4 + mi) * 4 + ktl) * 512 + lane * 16);
                LDS128(ah[mi][0], ah[mi][1], ah[mi][2], ah[mi][3], stg + OFF_AH + off);
                LDS128(al[mi][0], al[mi][1], al[mi][2], al[mi][3], stg + OFF_AL + off);
            }
            #pragma unroll
            for (int ni = 0; ni < 8; ni++) {
                uint32_t off = (uint32_t)(((wn * 8 + ni) * 4 + ktl) * 256 + lane * 8);
                LDS64(bh[ni][0], bh[ni][1], stg + OFF_BH + off);
                LDS64(bl[ni][0], bl[ni][1], stg + OFF_BL + off);
            }
            #pragma unroll
            for (int mi = 0; mi < 4; mi++)
                #pragma unroll
                for (int ni = 0; ni < 8; ni++) {
                    float* c = acc[mi][ni];
                    mma_tf32(c[0], c[1], c[2], c[3],
                             ah[mi][0], ah[mi][1], ah[mi][2], ah[mi][3],
                             bh[ni][0], bh[ni][1]);
                    mma_tf32(c[0], c[1], c[2], c[3],
                             ah[mi][0], ah[mi][1], ah[mi][2], ah[mi][3],
                             bl[ni][0], bl[ni][1]);
                    mma_tf32(c[0], c[1], c[2], c[3],
                             al[mi][0], al[mi][1], al[mi][2], al[mi][3],
                             bh[ni][0], bh[ni][1]);
                }
        }
        __syncthreads();
        if (tid == 0 && it + STAGES < NITER)
            issue_stage(sb, s, mt0, (it + STAGES) * 4);
    }

    // epilogue: sigmoid -> g_scores
    const int gp = lane >> 2, tg = lane & 3;
    const int bm = blockIdx.x * 128;
    #pragma unroll
    for (int mi = 0; mi < 4; mi++) {
        int r0 = bm + (wm * 4 + mi) * 16 + gp;
        #pragma unroll
        for (int ni = 0; ni < 8; ni++) {
            int cc = (wn * 8 + ni) * 8 + tg * 2;
            float* c = acc[mi][ni];
            float2 lo = make_float2(1.0f / (1.0f + expf(-c[0])),
                                    1.0f / (1.0f + expf(-c[1])));
            float2 hi = make_float2(1.0f / (1.0f + expf(-c[2])),
                                    1.0f / (1.0f + expf(-c[3])));
            *(float2*)(g_scores + (size_t)r0 * NEXP + cc) = lo;
            *(float2*)(g_scores + (size_t)(r0 + 8) * NEXP + cc) = hi;
        }
    }
}

// ---------------------------------------------------------------------------
// Routing core (warp-wide). s/ch are per-lane 8 scores (experts lane*8..+8).
// ---------------------------------------------------------------------------
__device__ __forceinline__ void route_core(const float s[8], const float ch[8],
                                           int lane, int t, float* out,
                                           bool do_margin, float* margin_e, float* margin_g)
{
    const unsigned FULL = 0xffffffffu;
    float m1 = -FLT_MAX, m2 = -FLT_MAX;
    #pragma unroll
    for (int j = 0; j < 8; j++) {
        float v = ch[j];
        if (v > m1) { m2 = m1; m1 = v; }
        else if (v > m2) { m2 = v; }
    }
    #pragma unroll
    for (int off = 1; off < 4; off <<= 1) {
        float om1 = __shfl_xor_sync(FULL, m1, off);
        float om2 = __shfl_xor_sync(FULL, m2, off);
        if (om1 > m1) { m2 = fmaxf(m1, om2); m1 = om1; }
        else          { m2 = fmaxf(m2, om1); }
    }
    float gs = m1 + m2;
    float gsv[8];
    #pragma unroll
    for (int g = 0; g < 8; g++) gsv[g] = __shfl_sync(FULL, gs, g * 4);

    unsigned gmask = 0;
    float bv4 = -FLT_MAX;
    #pragma unroll
    for (int r = 0; r < TOPKG; r++) {
        float bv = -FLT_MAX; int bi = 0;
        #pragma unroll
        for (int g = 0; g < 8; g++) {
            bool used = (gmask >> g) & 1u;
            if (!used && gsv[g] > bv) { bv = gsv[g]; bi = g; }
        }
        gmask |= (1u << bi);
        bv4 = bv;
    }
    if (do_margin) {
        float g5 = -FLT_MAX;
        #pragma unroll
        for (int g = 0; g < 8; g++)
            if (!((gmask >> g) & 1u) && gsv[g] > g5) g5 = gsv[g];
        *margin_g = bv4 - g5;
    }

    float tmp[8];
    bool gon = (gmask >> (lane >> 2)) & 1u;
    #pragma unroll
    for (int j = 0; j < 8; j++) tmp[j] = gon ? ch[j] : 0.0f;

    int   idxs[TOPK];
    float wts[TOPK];
    float wsum = 0.0f;
    float prevv = FLT_MAX, mgap = FLT_MAX;
    const int NROUND = 9;   // extra round only read when do_margin
    #pragma unroll
    for (int r = 0; r < NROUND; r++) {
        float bv = -FLT_MAX; int bj = 0;
        #pragma unroll
        for (int j = 0; j < 8; j++)
            if (tmp[j] > bv) { bv = tmp[j]; bj = j; }
        int gi = lane * 8 + bj;
        #pragma unroll
        for (int off = 16; off > 0; off >>= 1) {
            float ov = __shfl_xor_sync(FULL, bv, off);
            int   oi = __shfl_xor_sync(FULL, gi, off);
            if (ov > bv || (ov == bv && oi < gi)) { bv = ov; gi = oi; }
        }
        if (r > 0) mgap = fminf(mgap, prevv - bv);
        prevv = bv;
        if (r < TOPK) {
            float myw = s[gi & 7];
            float wv = __shfl_sync(FULL, myw, gi >> 3);
            if ((gi >> 3) == lane) tmp[gi & 7] = -FLT_MAX;
            idxs[r] = gi;
            wts[r]  = wv;
            wsum   += wv;
        }
        if (!do_margin && r == TOPK - 1) break;
    }
    if (do_margin) *margin_e = mgap;

    if (lane == 0) {
        float denom = wsum + 1e-20f;
        #pragma unroll
        for (int r = 0; r < TOPK; r++) {
            out[(size_t)t * TOPK + r] = (float)idxs[r];
            out[(size_t)T_TOKENS * TOPK + (size_t)t * TOPK + r] =
                (wts[r] / denom) * 2.5f;
        }
    }
}

// ---------------------------------------------------------------------------
// Routing kernel: one warp per token, margin check + flagging.
// ---------------------------------------------------------------------------
__global__ __launch_bounds__(256) void route_kernel(
    const float* __restrict__ bias, float* __restrict__ out)
{
    const int warp = threadIdx.x >> 5;
    const int lane = threadIdx.x & 31;
    const int t = blockIdx.x * 8 + warp;

    const float* sp = g_scores + (size_t)t * NEXP + lane * 8;
    float s[8], ch[8];
    float4 v0 = *(const float4*)(sp);
    float4 v1 = *(const float4*)(sp + 4);
    s[0]=v0.x; s[1]=v0.y; s[2]=v0.z; s[3]=v0.w;
    s[4]=v1.x; s[5]=v1.y; s[6]=v1.z; s[7]=v1.w;
    const float* bp = bias + lane * 8;
    float4 b0 = *(const float4*)(bp);
    float4 b1 = *(const float4*)(bp + 4);
    ch[0]=s[0]+b0.x; ch[1]=s[1]+b0.y; ch[2]=s[2]+b0.z; ch[3]=s[3]+b0.w;
    ch[4]=s[4]+b1.x; ch[5]=s[5]+b1.y; ch[6]=s[6]+b1.z; ch[7]=s[7]+b1.w;

    float me, mg;
    route_core(s, ch, lane, t, out, true, &me, &mg);

    if (lane == 0 && (me < TAU_E || mg < TAU_G)) {
        int p = atomicAdd(&g_nflag, 1);
        g_flaglist[p] = t;
    }
}

// ---------------------------------------------------------------------------
// Fixup: recompute flagged tokens with bitwise-R1 sequential fp32 FFMA.
// One token per grid-stride iteration; 256 threads (one per expert).
// ---------------------------------------------------------------------------
__global__ __launch_bounds__(256) void fixup_kernel(
    const float* __restrict__ x, const float* __restrict__ w,
    const float* __restrict__ bias, float* __restrict__ out)
{
    __shared__ float xs[HDIM];
    __shared__ float ws[256 * 33];
    __shared__ float sc[NEXP];
    const int tid = threadIdx.x;
    const int nf = g_nflag;

    for (int fi = blockIdx.x; fi < nf; fi += gridDim.x) {
        const int t = g_flaglist[fi];
        __syncthreads();
        #pragma unroll
        for (int i = 0; i < HDIM / 256; i++)
            xs[tid + i * 256] = x[(size_t)t * HDIM + tid + i * 256];
        float acc = 0.0f;
        for (int kc = 0; kc < 64; kc++) {
            __syncthreads();
            #pragma unroll
            for (int j = 0; j < 32; j++) {
                int idx = tid + j * 256;
                int er = idx >> 5, kk = idx & 31;
                ws[er * 33 + kk] = w[(size_t)er * HDIM + kc * 32 + kk];
            }
            __syncthreads();
            const float* xk = xs + kc * 32;
            const float* we = ws + tid * 33;
            #pragma unroll
            for (int k = 0; k < 32; k++)
                acc = fmaf(xk[k], we[k], acc);   // ascending k: bitwise R1 order
        }
        sc[tid] = 1.0f / (1.0f + expf(-acc));
        __syncthreads();
        if (tid < 32) {
            const int lane = tid;
            float s[8], ch[8];
            #pragma unroll
            for (int j = 0; j < 8; j++) {
                s[j]  = sc[lane * 8 + j];
                ch[j] = s[j] + bias[lane * 8 + j];
            }
            float me, mg;
            route_core(s, ch, lane, t, out, false, &me, &mg);
        }
    }
}

// ---------------------------------------------------------------------------
extern "C" void kernel_launch(void* const* d_in, const int* in_sizes, int n_in,
                              void* d_out, int out_size)
{
    const float* x    = (const float*)d_in[0];   // [4,4096,2048]
    const float* w    = (const float*)d_in[1];   // [256,2048]
    const float* bias = (const float*)d_in[2];   // [256]
    float* out = (float*)d_out;

    cudaFuncSetAttribute(gemm_mma_kernel,
                         cudaFuncAttributeMaxDynamicSharedMemorySize, SMEM_SZ);

    split_a_kernel<<<(T_TOKENS / 16) * (HDIM / 8) / 8, 256>>>(x);
    split_b_kernel<<<(NEXP / 8) * (HDIM / 8) / 8, 256>>>(w);
    gemm_mma_kernel<<<T_TOKENS / 128, 256, SMEM_SZ>>>();
    route_kernel<<<T_TOKENS / 8, 256>>>(bias, out);
    fixup_kernel<<<512, 256>>>(x, w, bias, out);
}

// round 6
// speedup vs baseline: 1.3823x; 1.3823x over previous
#include <cuda_runtime.h>
#include <cuda_fp16.h>
#include <math.h>
#include <float.h>
#include <stdint.h>

#define T_TOKENS 16384
#define HDIM     2048
#define NEXP     256
#define TOPK     8
#define TOPKG    4

#define TAU_E 3e-5f
#define TAU_G 6e-5f

#define MT_TILES (T_TOKENS / 16)   // 1024
#define KT_TILES (HDIM / 16)       // 128
#define NT_TILES (NEXP / 8)        // 32

// ---------------- static device scratch ----------------
__device__ float g_scores[(size_t)T_TOKENS * NEXP];                        // 16 MB
// A fragments (fp16x2 packed), [mt][kt][128 u32], h1/h2 separate
__device__ __align__(16) uint32_t g_Ah1[(size_t)MT_TILES * KT_TILES * 128]; // 67 MB
__device__ __align__(16) uint32_t g_Ah2[(size_t)MT_TILES * KT_TILES * 128]; // 67 MB
// B fragments, stage-contiguous: [ks(64)][nt(32)][kt2(2)][64 u32]
__device__ __align__(16) uint32_t g_Bh1[64 * 32 * 2 * 64];                  // 1 MB
__device__ __align__(16) uint32_t g_Bh2[64 * 32 * 2 * 64];                  // 1 MB
__device__ int   g_nflag;
__device__ int   g_flaglist[T_TOKENS];

// ---------------- helpers ----------------
__device__ __forceinline__ uint32_t smem_u32(const void* p) {
    uint32_t a;
    asm("{ .reg .u64 t; cvta.to.shared.u64 t, %1; cvt.u32.u64 %0, t; }" : "=r"(a) : "l"(p));
    return a;
}
__device__ __forceinline__ uint32_t pack_h2(__half lo, __half hi) {
    return (uint32_t)__half_as_ushort(lo) | ((uint32_t)__half_as_ushort(hi) << 16);
}
__device__ __forceinline__ void split2(float p, float q, uint32_t& hi, uint32_t& lo) {
    __half hp = __float2half_rn(p);
    __half hq = __float2half_rn(q);
    __half rp = __float2half_rn(p - __half2float(hp));
    __half rq = __float2half_rn(q - __half2float(hq));
    hi = pack_h2(hp, hq);   // low half = p (first k of the pair)
    lo = pack_h2(rp, rq);
}
#define MBAR_INIT(a, n) \
    asm volatile("mbarrier.init.shared.b64 [%0], %1;" :: "r"(a), "r"((uint32_t)(n)) : "memory")
#define MBAR_EXPECT_TX(a, b) \
    asm volatile("mbarrier.arrive.expect_tx.shared.b64 _, [%0], %1;" :: "r"(a), "r"((uint32_t)(b)) : "memory")
#define MBAR_WAIT(a, ph) do {                                                   \
    uint32_t _m = (a); uint32_t _p = (ph); uint32_t _d;                         \
    asm volatile("{\n .reg .pred p;\n"                                          \
        " mbarrier.try_wait.parity.acquire.cta.shared::cta.b64 p, [%1], %2;\n"  \
        " selp.b32 %0, 1, 0, p;\n}" : "=r"(_d) : "r"(_m), "r"(_p) : "memory");  \
    if (!_d) {                                                                  \
        asm volatile("{\n .reg .pred P1;\n"                                     \
            "W_%=:\n"                                                           \
            " mbarrier.try_wait.parity.acquire.cta.shared::cta.b64 P1, [%0], %1, 0x989680;\n" \
            " @P1 bra.uni D_%=;\n bra.uni W_%=;\n"                              \
            "D_%=:\n}" :: "r"(_m), "r"(_p) : "memory");                         \
    } } while (0)

__device__ __forceinline__ void bulk_g2s(uint32_t dst, const void* src, uint32_t bytes, uint32_t mbar) {
    asm volatile(
        "cp.async.bulk.shared::cluster.global.mbarrier::complete_tx::bytes [%0], [%1], %2, [%3];"
        :: "r"(dst), "l"(src), "r"(bytes), "r"(mbar) : "memory");
}
__device__ __forceinline__ void mma_f16(float& c0, float& c1, float& c2, float& c3,
                                        uint32_t a0, uint32_t a1, uint32_t a2, uint32_t a3,
                                        uint32_t b0, uint32_t b1) {
    asm volatile(
        "mma.sync.aligned.m16n8k16.row.col.f32.f16.f16.f32 "
        "{%0,%1,%2,%3}, {%4,%5,%6,%7}, {%8,%9}, {%0,%1,%2,%3};"
        : "+f"(c0), "+f"(c1), "+f"(c2), "+f"(c3)
        : "r"(a0), "r"(a1), "r"(a2), "r"(a3), "r"(b0), "r"(b1));
}
#define LDS128(r0, r1, r2, r3, a) \
    asm volatile("ld.shared.v4.b32 {%0,%1,%2,%3}, [%4];" : "=r"(r0), "=r"(r1), "=r"(r2), "=r"(r3) : "r"(a))
#define LDS64(r0, r1, a) \
    asm volatile("ld.shared.v2.b32 {%0,%1}, [%2];" : "=r"(r0), "=r"(r1) : "r"(a))

// ---------------------------------------------------------------------------
// split_a: x -> fp16 hi/lo fragment tiles. One warp per 16x16 tile.
// Frag (m16n8k16 A): a0=(g,2t:2t+1) a1=(g+8,2t:2t+1) a2=(g,2t+8:2t+9) a3=(g+8,2t+8:2t+9)
// ---------------------------------------------------------------------------
__global__ __launch_bounds__(256) void split_a_kernel(const float* __restrict__ x) {
    int tile = blockIdx.x * 8 + (threadIdx.x >> 5);   // mt*128 + kt
    int lane = threadIdx.x & 31;
    int mt = tile >> 7;
    int kt = tile & 127;
    int g = lane >> 2, t = lane & 3;
    const float* base = x + (size_t)(mt * 16) * HDIM + kt * 16;
    float2 v00 = *(const float2*)(base + (size_t)g * HDIM + 2 * t);
    float2 v10 = *(const float2*)(base + (size_t)(g + 8) * HDIM + 2 * t);
    float2 v01 = *(const float2*)(base + (size_t)g * HDIM + 2 * t + 8);
    float2 v11 = *(const float2*)(base + (size_t)(g + 8) * HDIM + 2 * t + 8);
    uint32_t h[4], l[4];
    split2(v00.x, v00.y, h[0], l[0]);
    split2(v10.x, v10.y, h[1], l[1]);
    split2(v01.x, v01.y, h[2], l[2]);
    split2(v11.x, v11.y, h[3], l[3]);
    size_t o = (size_t)tile * 128 + lane * 4;
    *(uint4*)(g_Ah1 + o) = make_uint4(h[0], h[1], h[2], h[3]);
    *(uint4*)(g_Ah2 + o) = make_uint4(l[0], l[1], l[2], l[3]);
}

// ---------------------------------------------------------------------------
// split_b: w -> fp16 hi/lo B fragments, stage-contiguous.
// Frag (m16n8k16 B, col): b0=(k=2t:2t+1, n=g) b1=(k=2t+8:2t+9, n=g)
// ---------------------------------------------------------------------------
__global__ __launch_bounds__(256) void split_b_kernel(const float* __restrict__ w) {
    if (blockIdx.x == 0 && threadIdx.x == 0) g_nflag = 0;
    int tile = blockIdx.x * 8 + (threadIdx.x >> 5);   // nt*128 + kt
    int lane = threadIdx.x & 31;
    int nt = tile >> 7;
    int kt = tile & 127;
    int ks = kt >> 1, kt2 = kt & 1;
    int g = lane >> 2, t = lane & 3;
    const float* base = w + (size_t)(nt * 8 + g) * HDIM + kt * 16;
    float2 u0 = *(const float2*)(base + 2 * t);
    float2 u1 = *(const float2*)(base + 2 * t + 8);
    uint32_t b0h, b0l, b1h, b1l;
    split2(u0.x, u0.y, b0h, b0l);
    split2(u1.x, u1.y, b1h, b1l);
    size_t o = (size_t)(((ks * 32 + nt) * 2 + kt2)) * 64 + lane * 2;
    g_Bh1[o] = b0h; g_Bh1[o + 1] = b1h;
    g_Bh2[o] = b0l; g_Bh2[o + 1] = b1l;
}

// ---------------------------------------------------------------------------
// GEMM: 3x fp16 mma.sync (2-term split), BM=128 BN=256 BK=32, 4-stage pipeline
// stage: Ah1 8K | Ah2 8K | Bh1 16K | Bh2 16K = 48K
// ---------------------------------------------------------------------------
#define STAGES   4
#define STG_SZ   49152
#define OFF_AH1  0
#define OFF_AH2  8192
#define OFF_BH1  16384
#define OFF_BH2  32768
#define OFF_MBAR (STAGES * STG_SZ)
#define SMEM_SZ  (OFF_MBAR + 64)
#define NITER    (HDIM / 32)   // 64

__device__ __forceinline__ void issue_stage(uint32_t sb, int s, int mt0, int ks) {
    uint32_t stg = sb + s * STG_SZ;
    uint32_t mb  = sb + OFF_MBAR + s * 8;
    MBAR_EXPECT_TX(mb, STG_SZ);
    #pragma unroll
    for (int i = 0; i < 8; i++) {
        size_t src = ((size_t)(mt0 + i) * 128 + ks * 2) * 128;
        bulk_g2s(stg + OFF_AH1 + i * 1024, g_Ah1 + src, 1024, mb);
        bulk_g2s(stg + OFF_AH2 + i * 1024, g_Ah2 + src, 1024, mb);
    }
    size_t bs = (size_t)ks * 4096;
    bulk_g2s(stg + OFF_BH1, g_Bh1 + bs, 16384, mb);
    bulk_g2s(stg + OFF_BH2, g_Bh2 + bs, 16384, mb);
}

__global__ __launch_bounds__(256, 1) void gemm_mma_kernel() {
    extern __shared__ __align__(1024) char smem[];
    const uint32_t sb = smem_u32(smem);
    const int tid  = threadIdx.x;
    const int wid  = tid >> 5;
    const int lane = tid & 31;
    const int wm   = wid >> 2;          // 0..1 (64 rows each)
    const int wn   = wid & 3;           // 0..3 (64 cols each)
    const int mt0  = blockIdx.x * 8;

    if (tid == 0) {
        #pragma unroll
        for (int s = 0; s < STAGES; s++) MBAR_INIT(sb + OFF_MBAR + s * 8, 1);
    }
    __syncthreads();
    if (tid == 0) {
        #pragma unroll
        for (int s = 0; s < STAGES; s++) issue_stage(sb, s, mt0, s);
    }

    float acc[4][8][4];
    #pragma unroll
    for (int i = 0; i < 4; i++)
        #pragma unroll
        for (int j = 0; j < 8; j++)
            #pragma unroll
            for (int q = 0; q < 4; q++) acc[i][j][q] = 0.0f;

    int ph[STAGES] = {0, 0, 0, 0};

    for (int it = 0; it < NITER; it++) {
        const int s = it & (STAGES - 1);
        const uint32_t stg = sb + s * STG_SZ;
        MBAR_WAIT(sb + OFF_MBAR + s * 8, ph[s]);
        ph[s] ^= 1;

        #pragma unroll
        for (int kt2 = 0; kt2 < 2; kt2++) {
            uint32_t ah[4][4], al[4][4], bh[8][2], bl[8][2];
            #pragma unroll
            for (int mi = 0; mi < 4; mi++) {
                uint32_t off = (uint32_t)(((wm * 4 + mi) * 2 + kt2) * 512 + lane * 16);
                LDS128(ah[mi][0], ah[mi][1], ah[mi][2], ah[mi][3], stg + OFF_AH1 + off);
                LDS128(al[mi][0], al[mi][1], al[mi][2], al[mi][3], stg + OFF_AH2 + off);
            }
            #pragma unroll
            for (int ni = 0; ni < 8; ni++) {
                uint32_t off = (uint32_t)(((wn * 8 + ni) * 2 + kt2) * 256 + lane * 8);
                LDS64(bh[ni][0], bh[ni][1], stg + OFF_BH1 + off);
                LDS64(bl[ni][0], bl[ni][1], stg + OFF_BH2 + off);
            }
            #pragma unroll
            for (int mi = 0; mi < 4; mi++)
                #pragma unroll
                for (int ni = 0; ni < 8; ni++) {
                    float* c = acc[mi][ni];
                    mma_f16(c[0], c[1], c[2], c[3],
                            ah[mi][0], ah[mi][1], ah[mi][2], ah[mi][3],
                            bh[ni][0], bh[ni][1]);
                    mma_f16(c[0], c[1], c[2], c[3],
                            ah[mi][0], ah[mi][1], ah[mi][2], ah[mi][3],
                            bl[ni][0], bl[ni][1]);
                    mma_f16(c[0], c[1], c[2], c[3],
                            al[mi][0], al[mi][1], al[mi][2], al[mi][3],
                            bh[ni][0], bh[ni][1]);
                }
        }
        __syncthreads();
        if (tid == 0 && it + STAGES < NITER)
            issue_stage(sb, s, mt0, it + STAGES);
    }

    // epilogue: sigmoid -> g_scores
    const int g = lane >> 2, t = lane & 3;
    const int bm = blockIdx.x * 128;
    #pragma unroll
    for (int mi = 0; mi < 4; mi++) {
        int r0 = bm + (wm * 4 + mi) * 16 + g;
        #pragma unroll
        for (int ni = 0; ni < 8; ni++) {
            int cc = (wn * 8 + ni) * 8 + t * 2;
            float* c = acc[mi][ni];
            float2 lo = make_float2(1.0f / (1.0f + expf(-c[0])),
                                    1.0f / (1.0f + expf(-c[1])));
            float2 hi = make_float2(1.0f / (1.0f + expf(-c[2])),
                                    1.0f / (1.0f + expf(-c[3])));
            *(float2*)(g_scores + (size_t)r0 * NEXP + cc) = lo;
            *(float2*)(g_scores + (size_t)(r0 + 8) * NEXP + cc) = hi;
        }
    }
}

// ---------------------------------------------------------------------------
// Routing core (warp-wide), identical semantics to validated R1/R4.
// ---------------------------------------------------------------------------
__device__ __forceinline__ void route_core(const float s[8], const float ch[8],
                                           int lane, int t, float* out,
                                           bool do_margin, float* margin_e, float* margin_g)
{
    const unsigned FULL = 0xffffffffu;
    float m1 = -FLT_MAX, m2 = -FLT_MAX;
    #pragma unroll
    for (int j = 0; j < 8; j++) {
        float v = ch[j];
        if (v > m1) { m2 = m1; m1 = v; }
        else if (v > m2) { m2 = v; }
    }
    #pragma unroll
    for (int off = 1; off < 4; off <<= 1) {
        float om1 = __shfl_xor_sync(FULL, m1, off);
        float om2 = __shfl_xor_sync(FULL, m2, off);
        if (om1 > m1) { m2 = fmaxf(m1, om2); m1 = om1; }
        else          { m2 = fmaxf(m2, om1); }
    }
    float gs = m1 + m2;
    float gsv[8];
    #pragma unroll
    for (int g = 0; g < 8; g++) gsv[g] = __shfl_sync(FULL, gs, g * 4);

    unsigned gmask = 0;
    float bv4 = -FLT_MAX;
    #pragma unroll
    for (int r = 0; r < TOPKG; r++) {
        float bv = -FLT_MAX; int bi = 0;
        #pragma unroll
        for (int g = 0; g < 8; g++) {
            bool used = (gmask >> g) & 1u;
            if (!used && gsv[g] > bv) { bv = gsv[g]; bi = g; }
        }
        gmask |= (1u << bi);
        bv4 = bv;
    }
    if (do_margin) {
        float g5 = -FLT_MAX;
        #pragma unroll
        for (int g = 0; g < 8; g++)
            if (!((gmask >> g) & 1u) && gsv[g] > g5) g5 = gsv[g];
        *margin_g = bv4 - g5;
    }

    float tmp[8];
    bool gon = (gmask >> (lane >> 2)) & 1u;
    #pragma unroll
    for (int j = 0; j < 8; j++) tmp[j] = gon ? ch[j] : 0.0f;

    int   idxs[TOPK];
    float wts[TOPK];
    float wsum = 0.0f;
    float prevv = FLT_MAX, mgap = FLT_MAX;
    const int NROUND = 9;
    #pragma unroll
    for (int r = 0; r < NROUND; r++) {
        float bv = -FLT_MAX; int bj = 0;
        #pragma unroll
        for (int j = 0; j < 8; j++)
            if (tmp[j] > bv) { bv = tmp[j]; bj = j; }
        int gi = lane * 8 + bj;
        #pragma unroll
        for (int off = 16; off > 0; off >>= 1) {
            float ov = __shfl_xor_sync(FULL, bv, off);
            int   oi = __shfl_xor_sync(FULL, gi, off);
            if (ov > bv || (ov == bv && oi < gi)) { bv = ov; gi = oi; }
        }
        if (r > 0) mgap = fminf(mgap, prevv - bv);
        prevv = bv;
        if (r < TOPK) {
            float myw = s[gi & 7];
            float wv = __shfl_sync(FULL, myw, gi >> 3);
            if ((gi >> 3) == lane) tmp[gi & 7] = -FLT_MAX;
            idxs[r] = gi;
            wts[r]  = wv;
            wsum   += wv;
        }
        if (!do_margin && r == TOPK - 1) break;
    }
    if (do_margin) *margin_e = mgap;

    if (lane == 0) {
        float denom = wsum + 1e-20f;
        #pragma unroll
        for (int r = 0; r < TOPK; r++) {
            out[(size_t)t * TOPK + r] = (float)idxs[r];
            out[(size_t)T_TOKENS * TOPK + (size_t)t * TOPK + r] =
                (wts[r] / denom) * 2.5f;
        }
    }
}

// ---------------------------------------------------------------------------
// Routing kernel: one warp per token, margin check + flagging.
// ---------------------------------------------------------------------------
__global__ __launch_bounds__(256) void route_kernel(
    const float* __restrict__ bias, float* __restrict__ out)
{
    const int warp = threadIdx.x >> 5;
    const int lane = threadIdx.x & 31;
    const int t = blockIdx.x * 8 + warp;

    const float* sp = g_scores + (size_t)t * NEXP + lane * 8;
    float s[8], ch[8];
    float4 v0 = *(const float4*)(sp);
    float4 v1 = *(const float4*)(sp + 4);
    s[0]=v0.x; s[1]=v0.y; s[2]=v0.z; s[3]=v0.w;
    s[4]=v1.x; s[5]=v1.y; s[6]=v1.z; s[7]=v1.w;
    const float* bp = bias + lane * 8;
    float4 b0 = *(const float4*)(bp);
    float4 b1 = *(const float4*)(bp + 4);
    ch[0]=s[0]+b0.x; ch[1]=s[1]+b0.y; ch[2]=s[2]+b0.z; ch[3]=s[3]+b0.w;
    ch[4]=s[4]+b1.x; ch[5]=s[5]+b1.y; ch[6]=s[6]+b1.z; ch[7]=s[7]+b1.w;

    float me, mg;
    route_core(s, ch, lane, t, out, true, &me, &mg);

    if (lane == 0 && (me < TAU_E || mg < TAU_G)) {
        int p = atomicAdd(&g_nflag, 1);
        g_flaglist[p] = t;
    }
}

// ---------------------------------------------------------------------------
// Fixup: recompute flagged tokens with bitwise-R1 sequential fp32 FFMA.
// ---------------------------------------------------------------------------
__global__ __launch_bounds__(256) void fixup_kernel(
    const float* __restrict__ x, const float* __restrict__ w,
    const float* __restrict__ bias, float* __restrict__ out)
{
    __shared__ float xs[HDIM];
    __shared__ float ws[256 * 33];
    __shared__ float sc[NEXP];
    const int tid = threadIdx.x;
    const int nf = g_nflag;

    for (int fi = blockIdx.x; fi < nf; fi += gridDim.x) {
        const int t = g_flaglist[fi];
        __syncthreads();
        #pragma unroll
        for (int i = 0; i < HDIM / 256; i++)
            xs[tid + i * 256] = x[(size_t)t * HDIM + tid + i * 256];
        float acc = 0.0f;
        for (int kc = 0; kc < 64; kc++) {
            __syncthreads();
            #pragma unroll
            for (int j = 0; j < 32; j++) {
                int idx = tid + j * 256;
                int er = idx >> 5, kk = idx & 31;
                ws[er * 33 + kk] = w[(size_t)er * HDIM + kc * 32 + kk];
            }
            __syncthreads();
            const float* xk = xs + kc * 32;
            const float* we = ws + tid * 33;
            #pragma unroll
            for (int k = 0; k < 32; k++)
                acc = fmaf(xk[k], we[k], acc);   // ascending k: reference-matching order
        }
        sc[tid] = 1.0f / (1.0f + expf(-acc));
        __syncthreads();
        if (tid < 32) {
            const int lane = tid;
            float s[8], ch[8];
            #pragma unroll
            for (int j = 0; j < 8; j++) {
                s[j]  = sc[lane * 8 + j];
                ch[j] = s[j] + bias[lane * 8 + j];
            }
            float me, mg;
            route_core(s, ch, lane, t, out, false, &me, &mg);
        }
    }
}

// ---------------------------------------------------------------------------
extern "C" void kernel_launch(void* const* d_in, const int* in_sizes, int n_in,
                              void* d_out, int out_size)
{
    const float* x    = (const float*)d_in[0];   // [4,4096,2048]
    const float* w    = (const float*)d_in[1];   // [256,2048]
    const float* bias = (const float*)d_in[2];   // [256]
    float* out = (float*)d_out;

    cudaFuncSetAttribute(gemm_mma_kernel,
                         cudaFuncAttributeMaxDynamicSharedMemorySize, SMEM_SZ);

    split_a_kernel<<<MT_TILES * KT_TILES / 8, 256>>>(x);
    split_b_kernel<<<NT_TILES * KT_TILES / 8, 256>>>(w);
    gemm_mma_kernel<<<T_TOKENS / 128, 256, SMEM_SZ>>>();
    route_kernel<<<T_TOKENS / 8, 256>>>(bias, out);
    fixup_kernel<<<512, 256>>>(x, w, bias, out);
}

// round 7
// speedup vs baseline: 1.7289x; 1.2508x over previous
#include <cuda_runtime.h>
#include <cuda_fp16.h>
#include <math.h>
#include <float.h>
#include <stdint.h>

#define T_TOKENS 16384
#define HDIM     2048
#define NEXP     256
#define TOPK     8
#define TOPKG    4

#define TAU_E 3e-5f
#define TAU_G 6e-5f
#define FTOK  8          // fixup tokens per CTA batch

// ---------------- static device scratch ----------------
__device__ float g_scores[(size_t)T_TOKENS * NEXP];        // 16 MB
// B fragments, stage-contiguous: [ks(64)][nt(32)][kt2(2)][64 u32]
__device__ __align__(16) uint32_t g_Bh1[64 * 32 * 2 * 64];  // 1 MB
__device__ __align__(16) uint32_t g_Bh2[64 * 32 * 2 * 64];  // 1 MB
__device__ int   g_nflag;
__device__ int   g_flaglist[T_TOKENS];

// ---------------- helpers ----------------
__device__ __forceinline__ uint32_t smem_u32(const void* p) {
    uint32_t a;
    asm("{ .reg .u64 t; cvta.to.shared.u64 t, %1; cvt.u32.u64 %0, t; }" : "=r"(a) : "l"(p));
    return a;
}
__device__ __forceinline__ uint32_t pack_h2(__half lo, __half hi) {
    return (uint32_t)__half_as_ushort(lo) | ((uint32_t)__half_as_ushort(hi) << 16);
}
__device__ __forceinline__ void split2(float p, float q, uint32_t& hi, uint32_t& lo) {
    __half hp = __float2half_rn(p);
    __half hq = __float2half_rn(q);
    __half rp = __float2half_rn(p - __half2float(hp));
    __half rq = __float2half_rn(q - __half2float(hq));
    hi = pack_h2(hp, hq);
    lo = pack_h2(rp, rq);
}
#define MBAR_INIT(a, n) \
    asm volatile("mbarrier.init.shared.b64 [%0], %1;" :: "r"(a), "r"((uint32_t)(n)) : "memory")
#define MBAR_EXPECT_TX(a, b) \
    asm volatile("mbarrier.arrive.expect_tx.shared.b64 _, [%0], %1;" :: "r"(a), "r"((uint32_t)(b)) : "memory")
#define MBAR_WAIT(a, ph) do {                                                   \
    uint32_t _m = (a); uint32_t _p = (ph); uint32_t _d;                         \
    asm volatile("{\n .reg .pred p;\n"                                          \
        " mbarrier.try_wait.parity.acquire.cta.shared::cta.b64 p, [%1], %2;\n"  \
        " selp.b32 %0, 1, 0, p;\n}" : "=r"(_d) : "r"(_m), "r"(_p) : "memory");  \
    if (!_d) {                                                                  \
        asm volatile("{\n .reg .pred P1;\n"                                     \
            "W_%=:\n"                                                           \
            " mbarrier.try_wait.parity.acquire.cta.shared::cta.b64 P1, [%0], %1, 0x989680;\n" \
            " @P1 bra.uni D_%=;\n bra.uni W_%=;\n"                              \
            "D_%=:\n}" :: "r"(_m), "r"(_p) : "memory");                         \
    } } while (0)

__device__ __forceinline__ void bulk_g2s(uint32_t dst, const void* src, uint32_t bytes, uint32_t mbar) {
    asm volatile(
        "cp.async.bulk.shared::cluster.global.mbarrier::complete_tx::bytes [%0], [%1], %2, [%3];"
        :: "r"(dst), "l"(src), "r"(bytes), "r"(mbar) : "memory");
}
__device__ __forceinline__ void mma_f16(float& c0, float& c1, float& c2, float& c3,
                                        uint32_t a0, uint32_t a1, uint32_t a2, uint32_t a3,
                                        uint32_t b0, uint32_t b1) {
    asm volatile(
        "mma.sync.aligned.m16n8k16.row.col.f32.f16.f16.f32 "
        "{%0,%1,%2,%3}, {%4,%5,%6,%7}, {%8,%9}, {%0,%1,%2,%3};"
        : "+f"(c0), "+f"(c1), "+f"(c2), "+f"(c3)
        : "r"(a0), "r"(a1), "r"(a2), "r"(a3), "r"(b0), "r"(b1));
}
#define LDS128(r0, r1, r2, r3, a) \
    asm volatile("ld.shared.v4.b32 {%0,%1,%2,%3}, [%4];" : "=r"(r0), "=r"(r1), "=r"(r2), "=r"(r3) : "r"(a))
#define LDS64(r0, r1, a) \
    asm volatile("ld.shared.v2.b32 {%0,%1}, [%2];" : "=r"(r0), "=r"(r1) : "r"(a))
#define STS128(a, r0, r1, r2, r3) \
    asm volatile("st.shared.v4.b32 [%0], {%1,%2,%3,%4};" :: "r"(a), "r"(r0), "r"(r1), "r"(r2), "r"(r3) : "memory")

// ---------------------------------------------------------------------------
// split_b: w -> fp16 hi/lo B fragments, stage-contiguous.
// ---------------------------------------------------------------------------
__global__ __launch_bounds__(256) void split_b_kernel(const float* __restrict__ w) {
    if (blockIdx.x == 0 && threadIdx.x == 0) g_nflag = 0;
    int tile = blockIdx.x * 8 + (threadIdx.x >> 5);   // nt*128 + kt
    int lane = threadIdx.x & 31;
    int nt = tile >> 7;
    int kt = tile & 127;
    int ks = kt >> 1, kt2 = kt & 1;
    int g = lane >> 2, t = lane & 3;
    const float* base = w + (size_t)(nt * 8 + g) * HDIM + kt * 16;
    float2 u0 = *(const float2*)(base + 2 * t);
    float2 u1 = *(const float2*)(base + 2 * t + 8);
    uint32_t b0h, b0l, b1h, b1l;
    split2(u0.x, u0.y, b0h, b0l);
    split2(u1.x, u1.y, b1h, b1l);
    size_t o = (size_t)(((ks * 32 + nt) * 2 + kt2)) * 64 + lane * 2;
    g_Bh1[o] = b0h; g_Bh1[o + 1] = b1h;
    g_Bh2[o] = b0l; g_Bh2[o + 1] = b1l;
}

// ---------------------------------------------------------------------------
// GEMM: fused A-split (LDG->split->STS) + 3x fp16 mma.sync, BM=128 BN=256
// smem: A 2 bufs x (hi 8K | lo 8K) = 32K;  B 4 stages x (hi 16K | lo 16K) = 128K
// ---------------------------------------------------------------------------
#define BSTAGES  4
#define OFF_B    32768
#define B_STG_SZ 32768
#define OFF_MBAR (OFF_B + BSTAGES * B_STG_SZ)    // 163840
#define SMEM_SZ  (OFF_MBAR + 64)
#define NITER    (HDIM / 32)   // 64

__device__ __forceinline__ void issue_b(uint32_t sb, int s, int ks) {
    uint32_t stg = sb + OFF_B + s * B_STG_SZ;
    uint32_t mb  = sb + OFF_MBAR + s * 8;
    MBAR_EXPECT_TX(mb, B_STG_SZ);
    bulk_g2s(stg,         g_Bh1 + (size_t)ks * 4096, 16384, mb);
    bulk_g2s(stg + 16384, g_Bh2 + (size_t)ks * 4096, 16384, mb);
}

// Load this warp's 2 fragment blocks of the A stage (8 float2 per thread).
__device__ __forceinline__ void lda(const float* __restrict__ x, int bm, int ks,
                                    int wid, int g, int t, float2 pr[8]) {
    #pragma unroll
    for (int b = 0; b < 2; b++) {
        int bi = wid * 2 + b;
        int mt = bi >> 1, kt2 = bi & 1;
        const float* p = x + (size_t)(bm + mt * 16 + g) * HDIM + ks * 32 + kt2 * 16 + 2 * t;
        pr[b * 4 + 0] = *(const float2*)(p);
        pr[b * 4 + 1] = *(const float2*)(p + 8 * HDIM);
        pr[b * 4 + 2] = *(const float2*)(p + 8);
        pr[b * 4 + 3] = *(const float2*)(p + 8 * HDIM + 8);
    }
}
__device__ __forceinline__ void sts_a(uint32_t abuf, int wid, int lane, const float2 pr[8]) {
    #pragma unroll
    for (int b = 0; b < 2; b++) {
        int bi = wid * 2 + b;
        uint32_t h[4], l[4];
        #pragma unroll
        for (int j = 0; j < 4; j++)
            split2(pr[b * 4 + j].x, pr[b * 4 + j].y, h[j], l[j]);
        uint32_t dst = abuf + (uint32_t)bi * 512 + lane * 16;
        STS128(dst,        h[0], h[1], h[2], h[3]);
        STS128(dst + 8192, l[0], l[1], l[2], l[3]);
    }
}

__global__ __launch_bounds__(256, 1) void gemm_mma_kernel(const float* __restrict__ x) {
    extern __shared__ __align__(1024) char smem[];
    const uint32_t sb = smem_u32(smem);
    const int tid  = threadIdx.x;
    const int wid  = tid >> 5;
    const int lane = tid & 31;
    const int g    = lane >> 2, t = lane & 3;
    const int wm   = wid >> 2;          // 0..1 (64 rows each)
    const int wn   = wid & 3;           // 0..3 (64 cols each)
    const int bm   = blockIdx.x * 128;

    if (tid == 0) {
        #pragma unroll
        for (int s = 0; s < BSTAGES; s++) MBAR_INIT(sb + OFF_MBAR + s * 8, 1);
    }
    __syncthreads();
    if (tid == 0) {
        #pragma unroll
        for (int s = 0; s < BSTAGES; s++) issue_b(sb, s, s);
    }

    // prologue: stage 0 of A
    float2 pr[8];
    lda(x, bm, 0, wid, g, t, pr);
    sts_a(sb, wid, lane, pr);
    __syncthreads();

    float acc[4][8][4];
    #pragma unroll
    for (int i = 0; i < 4; i++)
        #pragma unroll
        for (int j = 0; j < 8; j++)
            #pragma unroll
            for (int q = 0; q < 4; q++) acc[i][j][q] = 0.0f;

    int ph[BSTAGES] = {0, 0, 0, 0};

    for (int it = 0; it < NITER; it++) {
        const int sB = it & (BSTAGES - 1);
        const uint32_t stgA = sb + (uint32_t)(it & 1) * 16384;
        const uint32_t stgB = sb + OFF_B + sB * B_STG_SZ;

        if (it + 1 < NITER) lda(x, bm, it + 1, wid, g, t, pr);   // prefetch A

        MBAR_WAIT(sb + OFF_MBAR + sB * 8, ph[sB]);
        ph[sB] ^= 1;

        #pragma unroll
        for (int kt2 = 0; kt2 < 2; kt2++) {
            uint32_t ah[4][4], al[4][4], bh[8][2], bl[8][2];
            #pragma unroll
            for (int mi = 0; mi < 4; mi++) {
                uint32_t off = (uint32_t)(((wm * 4 + mi) * 2 + kt2) * 512 + lane * 16);
                LDS128(ah[mi][0], ah[mi][1], ah[mi][2], ah[mi][3], stgA + off);
                LDS128(al[mi][0], al[mi][1], al[mi][2], al[mi][3], stgA + 8192 + off);
            }
            #pragma unroll
            for (int ni = 0; ni < 8; ni++) {
                uint32_t off = (uint32_t)(((wn * 8 + ni) * 2 + kt2) * 256 + lane * 8);
                LDS64(bh[ni][0], bh[ni][1], stgB + off);
                LDS64(bl[ni][0], bl[ni][1], stgB + 16384 + off);
            }
            #pragma unroll
            for (int mi = 0; mi < 4; mi++)
                #pragma unroll
                for (int ni = 0; ni < 8; ni++) {
                    float* c = acc[mi][ni];
                    mma_f16(c[0], c[1], c[2], c[3],
                            ah[mi][0], ah[mi][1], ah[mi][2], ah[mi][3],
                            bh[ni][0], bh[ni][1]);
                    mma_f16(c[0], c[1], c[2], c[3],
                            ah[mi][0], ah[mi][1], ah[mi][2], ah[mi][3],
                            bl[ni][0], bl[ni][1]);
                    mma_f16(c[0], c[1], c[2], c[3],
                            al[mi][0], al[mi][1], al[mi][2], al[mi][3],
                            bh[ni][0], bh[ni][1]);
                }
        }

        if (it + 1 < NITER)
            sts_a(sb + (uint32_t)((it + 1) & 1) * 16384, wid, lane, pr);
        __syncthreads();
        if (tid == 0 && it + BSTAGES < NITER)
            issue_b(sb, sB, it + BSTAGES);
    }

    // epilogue: sigmoid -> g_scores
    #pragma unroll
    for (int mi = 0; mi < 4; mi++) {
        int r0 = bm + (wm * 4 + mi) * 16 + g;
        #pragma unroll
        for (int ni = 0; ni < 8; ni++) {
            int cc = (wn * 8 + ni) * 8 + t * 2;
            float* c = acc[mi][ni];
            float2 lo = make_float2(1.0f / (1.0f + expf(-c[0])),
                                    1.0f / (1.0f + expf(-c[1])));
            float2 hi = make_float2(1.0f / (1.0f + expf(-c[2])),
                                    1.0f / (1.0f + expf(-c[3])));
            *(float2*)(g_scores + (size_t)r0 * NEXP + cc) = lo;
            *(float2*)(g_scores + (size_t)(r0 + 8) * NEXP + cc) = hi;
        }
    }
}

// ---------------------------------------------------------------------------
// Routing core (warp-wide), identical semantics to validated R1/R4/R6.
// ---------------------------------------------------------------------------
__device__ __forceinline__ void route_core(const float s[8], const float ch[8],
                                           int lane, int t, float* out,
                                           bool do_margin, float* margin_e, float* margin_g)
{
    const unsigned FULL = 0xffffffffu;
    float m1 = -FLT_MAX, m2 = -FLT_MAX;
    #pragma unroll
    for (int j = 0; j < 8; j++) {
        float v = ch[j];
        if (v > m1) { m2 = m1; m1 = v; }
        else if (v > m2) { m2 = v; }
    }
    #pragma unroll
    for (int off = 1; off < 4; off <<= 1) {
        float om1 = __shfl_xor_sync(FULL, m1, off);
        float om2 = __shfl_xor_sync(FULL, m2, off);
        if (om1 > m1) { m2 = fmaxf(m1, om2); m1 = om1; }
        else          { m2 = fmaxf(m2, om1); }
    }
    float gs = m1 + m2;
    float gsv[8];
    #pragma unroll
    for (int gg = 0; gg < 8; gg++) gsv[gg] = __shfl_sync(FULL, gs, gg * 4);

    unsigned gmask = 0;
    float bv4 = -FLT_MAX;
    #pragma unroll
    for (int r = 0; r < TOPKG; r++) {
        float bv = -FLT_MAX; int bi = 0;
        #pragma unroll
        for (int gg = 0; gg < 8; gg++) {
            bool used = (gmask >> gg) & 1u;
            if (!used && gsv[gg] > bv) { bv = gsv[gg]; bi = gg; }
        }
        gmask |= (1u << bi);
        bv4 = bv;
    }
    if (do_margin) {
        float g5 = -FLT_MAX;
        #pragma unroll
        for (int gg = 0; gg < 8; gg++)
            if (!((gmask >> gg) & 1u) && gsv[gg] > g5) g5 = gsv[gg];
        *margin_g = bv4 - g5;
    }

    float tmp[8];
    bool gon = (gmask >> (lane >> 2)) & 1u;
    #pragma unroll
    for (int j = 0; j < 8; j++) tmp[j] = gon ? ch[j] : 0.0f;

    int   idxs[TOPK];
    float wts[TOPK];
    float wsum = 0.0f;
    float prevv = FLT_MAX, mgap = FLT_MAX;
    const int NROUND = 9;
    #pragma unroll
    for (int r = 0; r < NROUND; r++) {
        float bv = -FLT_MAX; int bj = 0;
        #pragma unroll
        for (int j = 0; j < 8; j++)
            if (tmp[j] > bv) { bv = tmp[j]; bj = j; }
        int gi = lane * 8 + bj;
        #pragma unroll
        for (int off = 16; off > 0; off >>= 1) {
            float ov = __shfl_xor_sync(FULL, bv, off);
            int   oi = __shfl_xor_sync(FULL, gi, off);
            if (ov > bv || (ov == bv && oi < gi)) { bv = ov; gi = oi; }
        }
        if (r > 0) mgap = fminf(mgap, prevv - bv);
        prevv = bv;
        if (r < TOPK) {
            float myw = s[gi & 7];
            float wv = __shfl_sync(FULL, myw, gi >> 3);
            if ((gi >> 3) == lane) tmp[gi & 7] = -FLT_MAX;
            idxs[r] = gi;
            wts[r]  = wv;
            wsum   += wv;
        }
        if (!do_margin && r == TOPK - 1) break;
    }
    if (do_margin) *margin_e = mgap;

    if (lane == 0) {
        float denom = wsum + 1e-20f;
        #pragma unroll
        for (int r = 0; r < TOPK; r++) {
            out[(size_t)t * TOPK + r] = (float)idxs[r];
            out[(size_t)T_TOKENS * TOPK + (size_t)t * TOPK + r] =
                (wts[r] / denom) * 2.5f;
        }
    }
}

// ---------------------------------------------------------------------------
// Routing kernel: one warp per token, margin check + flagging.
// ---------------------------------------------------------------------------
__global__ __launch_bounds__(256) void route_kernel(
    const float* __restrict__ bias, float* __restrict__ out)
{
    const int warp = threadIdx.x >> 5;
    const int lane = threadIdx.x & 31;
    const int t = blockIdx.x * 8 + warp;

    const float* sp = g_scores + (size_t)t * NEXP + lane * 8;
    float s[8], ch[8];
    float4 v0 = *(const float4*)(sp);
    float4 v1 = *(const float4*)(sp + 4);
    s[0]=v0.x; s[1]=v0.y; s[2]=v0.z; s[3]=v0.w;
    s[4]=v1.x; s[5]=v1.y; s[6]=v1.z; s[7]=v1.w;
    const float* bp = bias + lane * 8;
    float4 b0 = *(const float4*)(bp);
    float4 b1 = *(const float4*)(bp + 4);
    ch[0]=s[0]+b0.x; ch[1]=s[1]+b0.y; ch[2]=s[2]+b0.z; ch[3]=s[3]+b0.w;
    ch[4]=s[4]+b1.x; ch[5]=s[5]+b1.y; ch[6]=s[6]+b1.z; ch[7]=s[7]+b1.w;

    float me, mg;
    route_core(s, ch, lane, t, out, true, &me, &mg);

    if (lane == 0 && (me < TAU_E || mg < TAU_G)) {
        int p = atomicAdd(&g_nflag, 1);
        g_flaglist[p] = t;
    }
}

// ---------------------------------------------------------------------------
// Fixup: recompute flagged tokens (batches of 8 per CTA) with sequential fp32
// FFMA in strictly ascending k (reference-matching order).
// dyn smem: xs[8][2048] | ws[256][33] | sc[8][256]  = 107,520 B
// ---------------------------------------------------------------------------
#define FIX_SMEM ((FTOK * HDIM + 256 * 33 + FTOK * NEXP) * 4)

__global__ __launch_bounds__(256) void fixup_kernel(
    const float* __restrict__ x, const float* __restrict__ w,
    const float* __restrict__ bias, float* __restrict__ out)
{
    extern __shared__ float fsm[];
    float* xs = fsm;                       // FTOK*HDIM
    float* ws = fsm + FTOK * HDIM;         // 256*33
    float* sc = ws + 256 * 33;             // FTOK*NEXP
    const int tid = threadIdx.x;
    const int nf = g_nflag;

    for (int base = blockIdx.x * FTOK; base < nf; base += gridDim.x * FTOK) {
        const int ntk = (nf - base < FTOK) ? (nf - base) : FTOK;
        __syncthreads();
        #pragma unroll
        for (int j = 0; j < FTOK; j++) {
            int tt = g_flaglist[base + (j < ntk ? j : 0)];
            for (int i = tid; i < HDIM; i += 256)
                xs[j * HDIM + i] = x[(size_t)tt * HDIM + i];
        }

        float acc[FTOK];
        #pragma unroll
        for (int j = 0; j < FTOK; j++) acc[j] = 0.0f;

        for (int kc = 0; kc < 64; kc++) {
            __syncthreads();
            #pragma unroll
            for (int jj = 0; jj < 32; jj++) {
                int idx = tid + jj * 256;
                int er = idx >> 5, kk = idx & 31;
                ws[er * 33 + kk] = w[(size_t)er * HDIM + kc * 32 + kk];
            }
            __syncthreads();
            const float* we = ws + tid * 33;
            #pragma unroll
            for (int k = 0; k < 32; k++) {
                float wv = we[k];
                #pragma unroll
                for (int j = 0; j < FTOK; j++)
                    acc[j] = fmaf(xs[j * HDIM + kc * 32 + k], wv, acc[j]);
            }
        }
        #pragma unroll
        for (int j = 0; j < FTOK; j++)
            sc[j * NEXP + tid] = 1.0f / (1.0f + expf(-acc[j]));
        __syncthreads();

        const int wid = tid >> 5, lane = tid & 31;
        if (wid < ntk) {
            int tt = g_flaglist[base + wid];
            float s[8], ch[8];
            #pragma unroll
            for (int j = 0; j < 8; j++) {
                s[j]  = sc[wid * NEXP + lane * 8 + j];
                ch[j] = s[j] + bias[lane * 8 + j];
            }
            float me, mg;
            route_core(s, ch, lane, tt, out, false, &me, &mg);
        }
    }
}

// ---------------------------------------------------------------------------
extern "C" void kernel_launch(void* const* d_in, const int* in_sizes, int n_in,
                              void* d_out, int out_size)
{
    const float* x    = (const float*)d_in[0];   // [4,4096,2048]
    const float* w    = (const float*)d_in[1];   // [256,2048]
    const float* bias = (const float*)d_in[2];   // [256]
    float* out = (float*)d_out;

    cudaFuncSetAttribute(gemm_mma_kernel,
                         cudaFuncAttributeMaxDynamicSharedMemorySize, SMEM_SZ);
    cudaFuncSetAttribute(fixup_kernel,
                         cudaFuncAttributeMaxDynamicSharedMemorySize, FIX_SMEM);

    split_b_kernel<<<(NEXP / 8) * (HDIM / 16) / 8, 256>>>(w);
    gemm_mma_kernel<<<T_TOKENS / 128, 256, SMEM_SZ>>>(x);
    route_kernel<<<T_TOKENS / 8, 256>>>(bias, out);
    fixup_kernel<<<64, 256, FIX_SMEM>>>(x, w, bias, out);
}

// round 9
// speedup vs baseline: 2.0051x; 1.1598x over previous
#include <cuda_runtime.h>
#include <cuda_fp16.h>
#include <math.h>
#include <float.h>
#include <stdint.h>

#define T_TOKENS 16384
#define HDIM     2048
#define NEXP     256
#define TOPK     8
#define TOPKG    4

#define TAU_E 1e-5f
#define TAU_G 2e-5f
#define FTOK  8          // fixup tokens per CTA batch

// ---------------- static device scratch ----------------
// B fragments, stage-contiguous: [ks(64)][nt(32)][kt2(2)][64 u32]
__device__ __align__(16) uint32_t g_Bh1[64 * 32 * 2 * 64];  // 1 MB
__device__ __align__(16) uint32_t g_Bh2[64 * 32 * 2 * 64];  // 1 MB
__device__ int   g_nflag;
__device__ int   g_flaglist[T_TOKENS];

// ---------------- helpers ----------------
__device__ __forceinline__ uint32_t smem_u32(const void* p) {
    uint32_t a;
    asm("{ .reg .u64 t; cvta.to.shared.u64 t, %1; cvt.u32.u64 %0, t; }" : "=r"(a) : "l"(p));
    return a;
}
__device__ __forceinline__ uint32_t pack_h2(__half lo, __half hi) {
    return (uint32_t)__half_as_ushort(lo) | ((uint32_t)__half_as_ushort(hi) << 16);
}
__device__ __forceinline__ void split2(float p, float q, uint32_t& hi, uint32_t& lo) {
    __half hp = __float2half_rn(p);
    __half hq = __float2half_rn(q);
    __half rp = __float2half_rn(p - __half2float(hp));
    __half rq = __float2half_rn(q - __half2float(hq));
    hi = pack_h2(hp, hq);
    lo = pack_h2(rp, rq);
}
#define MBAR_INIT(a, n) \
    asm volatile("mbarrier.init.shared.b64 [%0], %1;" :: "r"(a), "r"((uint32_t)(n)) : "memory")
#define MBAR_EXPECT_TX(a, b) \
    asm volatile("mbarrier.arrive.expect_tx.shared.b64 _, [%0], %1;" :: "r"(a), "r"((uint32_t)(b)) : "memory")
#define MBAR_WAIT(a, ph) do {                                                   \
    uint32_t _m = (a); uint32_t _p = (ph); uint32_t _d;                         \
    asm volatile("{\n .reg .pred p;\n"                                          \
        " mbarrier.try_wait.parity.acquire.cta.shared::cta.b64 p, [%1], %2;\n"  \
        " selp.b32 %0, 1, 0, p;\n}" : "=r"(_d) : "r"(_m), "r"(_p) : "memory");  \
    if (!_d) {                                                                  \
        asm volatile("{\n .reg .pred P1;\n"                                     \
            "W_%=:\n"                                                           \
            " mbarrier.try_wait.parity.acquire.cta.shared::cta.b64 P1, [%0], %1, 0x989680;\n" \
            " @P1 bra.uni D_%=;\n bra.uni W_%=;\n"                              \
            "D_%=:\n}" :: "r"(_m), "r"(_p) : "memory");                         \
    } } while (0)

__device__ __forceinline__ void bulk_g2s(uint32_t dst, const void* src, uint32_t bytes, uint32_t mbar) {
    asm volatile(
        "cp.async.bulk.shared::cluster.global.mbarrier::complete_tx::bytes [%0], [%1], %2, [%3];"
        :: "r"(dst), "l"(src), "r"(bytes), "r"(mbar) : "memory");
}
#define CP_ASYNC16(sa, gp) \
    asm volatile("cp.async.ca.shared.global [%0], [%1], 16;" :: "r"(sa), "l"(gp) : "memory")
#define CP_ASYNC4(sa, gp) \
    asm volatile("cp.async.ca.shared.global [%0], [%1], 4;" :: "r"(sa), "l"(gp) : "memory")
#define CP_COMMIT() asm volatile("cp.async.commit_group;" ::: "memory")
#define CP_WAIT(n)  asm volatile("cp.async.wait_group %0;" :: "n"(n) : "memory")

__device__ __forceinline__ void mma_f16(float& c0, float& c1, float& c2, float& c3,
                                        uint32_t a0, uint32_t a1, uint32_t a2, uint32_t a3,
                                        uint32_t b0, uint32_t b1) {
    asm volatile(
        "mma.sync.aligned.m16n8k16.row.col.f32.f16.f16.f32 "
        "{%0,%1,%2,%3}, {%4,%5,%6,%7}, {%8,%9}, {%0,%1,%2,%3};"
        : "+f"(c0), "+f"(c1), "+f"(c2), "+f"(c3)
        : "r"(a0), "r"(a1), "r"(a2), "r"(a3), "r"(b0), "r"(b1));
}
#define LDS128(r0, r1, r2, r3, a) \
    asm volatile("ld.shared.v4.b32 {%0,%1,%2,%3}, [%4];" : "=r"(r0), "=r"(r1), "=r"(r2), "=r"(r3) : "r"(a))
#define LDS64(r0, r1, a) \
    asm volatile("ld.shared.v2.b32 {%0,%1}, [%2];" : "=r"(r0), "=r"(r1) : "r"(a))
#define STS128(a, r0, r1, r2, r3) \
    asm volatile("st.shared.v4.b32 [%0], {%1,%2,%3,%4};" :: "r"(a), "r"(r0), "r"(r1), "r"(r2), "r"(r3) : "memory")

// ---------------------------------------------------------------------------
// Routing core (warp-wide), identical semantics to validated R1/R4/R6/R7.
// ---------------------------------------------------------------------------
__device__ __forceinline__ void route_core(const float s[8], const float ch[8],
                                           int lane, int t, float* out,
                                           bool do_margin, float* margin_e, float* margin_g)
{
    const unsigned FULL = 0xffffffffu;
    float m1 = -FLT_MAX, m2 = -FLT_MAX;
    #pragma unroll
    for (int j = 0; j < 8; j++) {
        float v = ch[j];
        if (v > m1) { m2 = m1; m1 = v; }
        else if (v > m2) { m2 = v; }
    }
    #pragma unroll
    for (int off = 1; off < 4; off <<= 1) {
        float om1 = __shfl_xor_sync(FULL, m1, off);
        float om2 = __shfl_xor_sync(FULL, m2, off);
        if (om1 > m1) { m2 = fmaxf(m1, om2); m1 = om1; }
        else          { m2 = fmaxf(m2, om1); }
    }
    float gs = m1 + m2;
    float gsv[8];
    #pragma unroll
    for (int gg = 0; gg < 8; gg++) gsv[gg] = __shfl_sync(FULL, gs, gg * 4);

    unsigned gmask = 0;
    float bv4 = -FLT_MAX;
    #pragma unroll
    for (int r = 0; r < TOPKG; r++) {
        float bv = -FLT_MAX; int bi = 0;
        #pragma unroll
        for (int gg = 0; gg < 8; gg++) {
            bool used = (gmask >> gg) & 1u;
            if (!used && gsv[gg] > bv) { bv = gsv[gg]; bi = gg; }
        }
        gmask |= (1u << bi);
        bv4 = bv;
    }
    if (do_margin) {
        float g5 = -FLT_MAX;
        #pragma unroll
        for (int gg = 0; gg < 8; gg++)
            if (!((gmask >> gg) & 1u) && gsv[gg] > g5) g5 = gsv[gg];
        *margin_g = bv4 - g5;
    }

    float tmp[8];
    bool gon = (gmask >> (lane >> 2)) & 1u;
    #pragma unroll
    for (int j = 0; j < 8; j++) tmp[j] = gon ? ch[j] : 0.0f;

    int   idxs[TOPK];
    float wts[TOPK];
    float wsum = 0.0f;
    float prevv = FLT_MAX, mgap = FLT_MAX;
    const int NROUND = 9;
    #pragma unroll
    for (int r = 0; r < NROUND; r++) {
        float bv = -FLT_MAX; int bj = 0;
        #pragma unroll
        for (int j = 0; j < 8; j++)
            if (tmp[j] > bv) { bv = tmp[j]; bj = j; }
        int gi = lane * 8 + bj;
        #pragma unroll
        for (int off = 16; off > 0; off >>= 1) {
            float ov = __shfl_xor_sync(FULL, bv, off);
            int   oi = __shfl_xor_sync(FULL, gi, off);
            if (ov > bv || (ov == bv && oi < gi)) { bv = ov; gi = oi; }
        }
        if (r > 0) mgap = fminf(mgap, prevv - bv);
        prevv = bv;
        if (r < TOPK) {
            float myw = s[gi & 7];
            float wv = __shfl_sync(FULL, myw, gi >> 3);
            if ((gi >> 3) == lane) tmp[gi & 7] = -FLT_MAX;
            idxs[r] = gi;
            wts[r]  = wv;
            wsum   += wv;
        }
        if (!do_margin && r == TOPK - 1) break;
    }
    if (do_margin) *margin_e = mgap;

    if (lane == 0) {
        float denom = wsum + 1e-20f;
        #pragma unroll
        for (int r = 0; r < TOPK; r++) {
            out[(size_t)t * TOPK + r] = (float)idxs[r];
            out[(size_t)T_TOKENS * TOPK + (size_t)t * TOPK + r] =
                (wts[r] / denom) * 2.5f;
        }
    }
}

// ---------------------------------------------------------------------------
// split_b: w -> fp16 hi/lo B fragments, stage-contiguous.
// ---------------------------------------------------------------------------
__global__ __launch_bounds__(256) void split_b_kernel(const float* __restrict__ w) {
    if (blockIdx.x == 0 && threadIdx.x == 0) g_nflag = 0;
    int tile = blockIdx.x * 8 + (threadIdx.x >> 5);   // nt*128 + kt
    int lane = threadIdx.x & 31;
    int nt = tile >> 7;
    int kt = tile & 127;
    int ks = kt >> 1, kt2 = kt & 1;
    int g = lane >> 2, t = lane & 3;
    const float* base = w + (size_t)(nt * 8 + g) * HDIM + kt * 16;
    float2 u0 = *(const float2*)(base + 2 * t);
    float2 u1 = *(const float2*)(base + 2 * t + 8);
    uint32_t b0h, b0l, b1h, b1l;
    split2(u0.x, u0.y, b0h, b0l);
    split2(u1.x, u1.y, b1h, b1l);
    size_t o = (size_t)(((ks * 32 + nt) * 2 + kt2)) * 64 + lane * 2;
    g_Bh1[o] = b0h; g_Bh1[o + 1] = b1h;
    g_Bh2[o] = b0l; g_Bh2[o + 1] = b1l;
}

// ---------------------------------------------------------------------------
// GEMM + fused routing: fused A-split + 3x fp16 mma.sync + sigmoid + route.
// smem: A 2x16K = 32K; B 4x32K = 128K; mbars. After mainloop the 160K region
// is reused as the score buffer [128 tokens][stride 260 f32] (130 KB).
// ---------------------------------------------------------------------------
#define BSTAGES  4
#define OFF_B    32768
#define B_STG_SZ 32768
#define OFF_MBAR (OFF_B + BSTAGES * B_STG_SZ)    // 163840
#define SMEM_SZ  (OFF_MBAR + 64)
#define NITER    (HDIM / 32)   // 64
#define SSTRIDE  260

__device__ __forceinline__ void issue_b(uint32_t sb, int s, int ks) {
    uint32_t stg = sb + OFF_B + s * B_STG_SZ;
    uint32_t mb  = sb + OFF_MBAR + s * 8;
    MBAR_EXPECT_TX(mb, B_STG_SZ);
    bulk_g2s(stg,         g_Bh1 + (size_t)ks * 4096, 16384, mb);
    bulk_g2s(stg + 16384, g_Bh2 + (size_t)ks * 4096, 16384, mb);
}

__device__ __forceinline__ void lda(const float* __restrict__ x, int bm, int ks,
                                    int wid, int g, int t, float2 pr[8]) {
    #pragma unroll
    for (int b = 0; b < 2; b++) {
        int bi = wid * 2 + b;
        int mt = bi >> 1, kt2 = bi & 1;
        const float* p = x + (size_t)(bm + mt * 16 + g) * HDIM + ks * 32 + kt2 * 16 + 2 * t;
        pr[b * 4 + 0] = *(const float2*)(p);
        pr[b * 4 + 1] = *(const float2*)(p + 8 * HDIM);
        pr[b * 4 + 2] = *(const float2*)(p + 8);
        pr[b * 4 + 3] = *(const float2*)(p + 8 * HDIM + 8);
    }
}
__device__ __forceinline__ void sts_a(uint32_t abuf, int wid, int lane, const float2 pr[8]) {
    #pragma unroll
    for (int b = 0; b < 2; b++) {
        int bi = wid * 2 + b;
        uint32_t h[4], l[4];
        #pragma unroll
        for (int j = 0; j < 4; j++)
            split2(pr[b * 4 + j].x, pr[b * 4 + j].y, h[j], l[j]);
        uint32_t dst = abuf + (uint32_t)bi * 512 + lane * 16;
        STS128(dst,        h[0], h[1], h[2], h[3]);
        STS128(dst + 8192, l[0], l[1], l[2], l[3]);
    }
}

__global__ __launch_bounds__(256, 1) void gemm_route_kernel(
    const float* __restrict__ x, const float* __restrict__ bias, float* __restrict__ out)
{
    extern __shared__ __align__(1024) char smem[];
    const uint32_t sb = smem_u32(smem);
    const int tid  = threadIdx.x;
    const int wid  = tid >> 5;
    const int lane = tid & 31;
    const int g    = lane >> 2, t = lane & 3;
    const int wm   = wid >> 2;
    const int wn   = wid & 3;
    const int bm   = blockIdx.x * 128;

    if (tid == 0) {
        #pragma unroll
        for (int s = 0; s < BSTAGES; s++) MBAR_INIT(sb + OFF_MBAR + s * 8, 1);
    }
    __syncthreads();
    if (tid == 0) {
        #pragma unroll
        for (int s = 0; s < BSTAGES; s++) issue_b(sb, s, s);
    }

    float2 pr[8];
    lda(x, bm, 0, wid, g, t, pr);
    sts_a(sb, wid, lane, pr);
    __syncthreads();

    float acc[4][8][4];
    #pragma unroll
    for (int i = 0; i < 4; i++)
        #pragma unroll
        for (int j = 0; j < 8; j++)
            #pragma unroll
            for (int q = 0; q < 4; q++) acc[i][j][q] = 0.0f;

    int ph[BSTAGES] = {0, 0, 0, 0};

    for (int it = 0; it < NITER; it++) {
        const int sB = it & (BSTAGES - 1);
        const uint32_t stgA = sb + (uint32_t)(it & 1) * 16384;
        const uint32_t stgB = sb + OFF_B + sB * B_STG_SZ;

        if (it + 1 < NITER) lda(x, bm, it + 1, wid, g, t, pr);

        MBAR_WAIT(sb + OFF_MBAR + sB * 8, ph[sB]);
        ph[sB] ^= 1;

        #pragma unroll
        for (int kt2 = 0; kt2 < 2; kt2++) {
            uint32_t ah[4][4], al[4][4], bh[8][2], bl[8][2];
            #pragma unroll
            for (int mi = 0; mi < 4; mi++) {
                uint32_t off = (uint32_t)(((wm * 4 + mi) * 2 + kt2) * 512 + lane * 16);
                LDS128(ah[mi][0], ah[mi][1], ah[mi][2], ah[mi][3], stgA + off);
                LDS128(al[mi][0], al[mi][1], al[mi][2], al[mi][3], stgA + 8192 + off);
            }
            #pragma unroll
            for (int ni = 0; ni < 8; ni++) {
                uint32_t off = (uint32_t)(((wn * 8 + ni) * 2 + kt2) * 256 + lane * 8);
                LDS64(bh[ni][0], bh[ni][1], stgB + off);
                LDS64(bl[ni][0], bl[ni][1], stgB + 16384 + off);
            }
            #pragma unroll
            for (int mi = 0; mi < 4; mi++)
                #pragma unroll
                for (int ni = 0; ni < 8; ni++) {
                    float* c = acc[mi][ni];
                    mma_f16(c[0], c[1], c[2], c[3],
                            ah[mi][0], ah[mi][1], ah[mi][2], ah[mi][3],
                            bh[ni][0], bh[ni][1]);
                    mma_f16(c[0], c[1], c[2], c[3],
                            ah[mi][0], ah[mi][1], ah[mi][2], ah[mi][3],
                            bl[ni][0], bl[ni][1]);
                    mma_f16(c[0], c[1], c[2], c[3],
                            al[mi][0], al[mi][1], al[mi][2], al[mi][3],
                            bh[ni][0], bh[ni][1]);
                }
        }

        if (it + 1 < NITER)
            sts_a(sb + (uint32_t)((it + 1) & 1) * 16384, wid, lane, pr);
        __syncthreads();
        if (tid == 0 && it + BSTAGES < NITER)
            issue_b(sb, sB, it + BSTAGES);
    }

    // ---------- epilogue: sigmoid -> smem score buffer (stage smem is dead) ----
    float* s_score = (float*)smem;
    #pragma unroll
    for (int mi = 0; mi < 4; mi++) {
        int r0 = (wm * 4 + mi) * 16 + g;
        #pragma unroll
        for (int ni = 0; ni < 8; ni++) {
            int cc = (wn * 8 + ni) * 8 + t * 2;
            float* c = acc[mi][ni];
            float2 lo = make_float2(1.0f / (1.0f + expf(-c[0])),
                                    1.0f / (1.0f + expf(-c[1])));
            float2 hi = make_float2(1.0f / (1.0f + expf(-c[2])),
                                    1.0f / (1.0f + expf(-c[3])));
            *(float2*)(s_score + (size_t)r0 * SSTRIDE + cc) = lo;
            *(float2*)(s_score + (size_t)(r0 + 8) * SSTRIDE + cc) = hi;
        }
    }
    __syncthreads();

    // ---------- fused routing: 8 warps x 16 tokens ----------
    const float* bp = bias + lane * 8;
    float4 bv0 = *(const float4*)(bp);
    float4 bv1 = *(const float4*)(bp + 4);
    for (int itok = 0; itok < 16; itok++) {
        const int m = wid * 16 + itok;
        const int tglob = bm + m;
        const float* sp = s_score + (size_t)m * SSTRIDE + lane * 8;
        float s[8], ch[8];
        float4 v0 = *(const float4*)(sp);
        float4 v1 = *(const float4*)(sp + 4);
        s[0]=v0.x; s[1]=v0.y; s[2]=v0.z; s[3]=v0.w;
        s[4]=v1.x; s[5]=v1.y; s[6]=v1.z; s[7]=v1.w;
        ch[0]=s[0]+bv0.x; ch[1]=s[1]+bv0.y; ch[2]=s[2]+bv0.z; ch[3]=s[3]+bv0.w;
        ch[4]=s[4]+bv1.x; ch[5]=s[5]+bv1.y; ch[6]=s[6]+bv1.z; ch[7]=s[7]+bv1.w;

        float me, mg;
        route_core(s, ch, lane, tglob, out, true, &me, &mg);

        if (lane == 0 && (me < TAU_E || mg < TAU_G)) {
            int p = atomicAdd(&g_nflag, 1);
            g_flaglist[p] = tglob;
        }
    }
}

// ---------------------------------------------------------------------------
// Fixup: recompute flagged tokens (batches of 8 per CTA) with sequential fp32
// FFMA in strictly ascending k (order identical to R7's validated fixup).
// Double-buffered w chunks via cp.async.
// dyn smem: xs[8][2048] | ws[2][256*33] | sc[8][256] = 141,312 B
// ---------------------------------------------------------------------------
#define WCH (256 * 33)
#define FIX_SMEM ((FTOK * HDIM + 2 * WCH + FTOK * NEXP) * 4)

__global__ __launch_bounds__(256) void fixup_kernel(
    const float* __restrict__ x, const float* __restrict__ w,
    const float* __restrict__ bias, float* __restrict__ out)
{
    extern __shared__ float fsm[];
    float* xs = fsm;                       // FTOK*HDIM
    float* ws = fsm + FTOK * HDIM;         // 2*WCH
    float* sc = ws + 2 * WCH;              // FTOK*NEXP
    const uint32_t fb = smem_u32(fsm);
    const uint32_t ws_base = fb + (uint32_t)(FTOK * HDIM) * 4;
    const int tid = threadIdx.x;
    const int nf = g_nflag;

    for (int base = blockIdx.x * FTOK; base < nf; base += gridDim.x * FTOK) {
        const int ntk = (nf - base < FTOK) ? (nf - base) : FTOK;
        __syncthreads();

        // xs via 16B cp.async
        #pragma unroll
        for (int j = 0; j < FTOK; j++) {
            int tt = g_flaglist[base + (j < ntk ? j : 0)];
            const float* src = x + (size_t)tt * HDIM;
            for (int i = tid * 4; i < HDIM; i += 1024)
                CP_ASYNC16(fb + (uint32_t)(j * HDIM + i) * 4, src + i);
        }
        // w chunk 0 via 4B cp.async (padded stride 33)
        #pragma unroll
        for (int jj = 0; jj < 32; jj++) {
            int idx = tid + jj * 256;
            int er = idx >> 5, kk = idx & 31;
            CP_ASYNC4(ws_base + (uint32_t)(er * 33 + kk) * 4, w + (size_t)er * HDIM + kk);
        }
        CP_COMMIT();

        float acc[FTOK];
        #pragma unroll
        for (int j = 0; j < FTOK; j++) acc[j] = 0.0f;

        for (int kc = 0; kc < 64; kc++) {
            const int bufc = kc & 1;
            if (kc + 1 < 64) {
                const uint32_t wb = ws_base + (uint32_t)((kc + 1) & 1) * (WCH * 4);
                #pragma unroll
                for (int jj = 0; jj < 32; jj++) {
                    int idx = tid + jj * 256;
                    int er = idx >> 5, kk = idx & 31;
                    CP_ASYNC4(wb + (uint32_t)(er * 33 + kk) * 4,
                              w + (size_t)er * HDIM + (kc + 1) * 32 + kk);
                }
                CP_COMMIT();
                CP_WAIT(1);
            } else {
                CP_WAIT(0);
            }
            __syncthreads();
            const float* we = ws + bufc * WCH + tid * 33;
            #pragma unroll
            for (int k = 0; k < 32; k++) {
                float wv = we[k];
                #pragma unroll
                for (int j = 0; j < FTOK; j++)
                    acc[j] = fmaf(xs[j * HDIM + kc * 32 + k], wv, acc[j]);
            }
            __syncthreads();
        }
        #pragma unroll
        for (int j = 0; j < FTOK; j++)
            sc[j * NEXP + tid] = 1.0f / (1.0f + expf(-acc[j]));
        __syncthreads();

        const int wid = tid >> 5, lane = tid & 31;
        if (wid < ntk) {
            int tt = g_flaglist[base + wid];
            float s[8], ch[8];
            #pragma unroll
            for (int j = 0; j < 8; j++) {
                s[j]  = sc[wid * NEXP + lane * 8 + j];
                ch[j] = s[j] + bias[lane * 8 + j];
            }
            float me, mg;
            route_core(s, ch, lane, tt, out, false, &me, &mg);
        }
    }
}

// ---------------------------------------------------------------------------
extern "C" void kernel_launch(void* const* d_in, const int* in_sizes, int n_in,
                              void* d_out, int out_size)
{
    const float* x    = (const float*)d_in[0];   // [4,4096,2048]
    const float* w    = (const float*)d_in[1];   // [256,2048]
    const float* bias = (const float*)d_in[2];   // [256]
    float* out = (float*)d_out;

    cudaFuncSetAttribute(gemm_route_kernel,
                         cudaFuncAttributeMaxDynamicSharedMemorySize, SMEM_SZ);
    cudaFuncSetAttribute(fixup_kernel,
                         cudaFuncAttributeMaxDynamicSharedMemorySize, FIX_SMEM);

    split_b_kernel<<<(NEXP / 8) * (HDIM / 16) / 8, 256>>>(w);
    gemm_route_kernel<<<T_TOKENS / 128, 256, SMEM_SZ>>>(x, bias, out);
    fixup_kernel<<<128, 256, FIX_SMEM>>>(x, w, bias, out);
}

// round 10
// speedup vs baseline: 2.0782x; 1.0365x over previous
#include <cuda_runtime.h>
#include <cuda_fp16.h>
#include <math.h>
#include <float.h>
#include <stdint.h>

#define T_TOKENS 16384
#define HDIM     2048
#define NEXP     256
#define TOPK     8
#define TOPKG    4

#define TAU_E 1e-5f
#define TAU_G 2e-5f
#define FTOK  8          // fixup tokens per CTA batch

// ---------------- static device scratch ----------------
__device__ float g_scores[(size_t)T_TOKENS * NEXP];         // 16 MB
// B fragments, stage-contiguous: [ks(64)][nt(32)][kt2(2)][64 u32]
__device__ __align__(16) uint32_t g_Bh1[64 * 32 * 2 * 64];  // 1 MB
__device__ __align__(16) uint32_t g_Bh2[64 * 32 * 2 * 64];  // 1 MB
__device__ int   g_nflag;
__device__ int   g_flaglist[T_TOKENS];

// ---------------- helpers ----------------
__device__ __forceinline__ uint32_t smem_u32(const void* p) {
    uint32_t a;
    asm("{ .reg .u64 t; cvta.to.shared.u64 t, %1; cvt.u32.u64 %0, t; }" : "=r"(a) : "l"(p));
    return a;
}
__device__ __forceinline__ uint32_t pack_h2(__half lo, __half hi) {
    return (uint32_t)__half_as_ushort(lo) | ((uint32_t)__half_as_ushort(hi) << 16);
}
__device__ __forceinline__ void split2(float p, float q, uint32_t& hi, uint32_t& lo) {
    __half hp = __float2half_rn(p);
    __half hq = __float2half_rn(q);
    __half rp = __float2half_rn(p - __half2float(hp));
    __half rq = __float2half_rn(q - __half2float(hq));
    hi = pack_h2(hp, hq);
    lo = pack_h2(rp, rq);
}
#define MBAR_INIT(a, n) \
    asm volatile("mbarrier.init.shared.b64 [%0], %1;" :: "r"(a), "r"((uint32_t)(n)) : "memory")
#define MBAR_EXPECT_TX(a, b) \
    asm volatile("mbarrier.arrive.expect_tx.shared.b64 _, [%0], %1;" :: "r"(a), "r"((uint32_t)(b)) : "memory")
#define MBAR_WAIT(a, ph) do {                                                   \
    uint32_t _m = (a); uint32_t _p = (ph); uint32_t _d;                         \
    asm volatile("{\n .reg .pred p;\n"                                          \
        " mbarrier.try_wait.parity.acquire.cta.shared::cta.b64 p, [%1], %2;\n"  \
        " selp.b32 %0, 1, 0, p;\n}" : "=r"(_d) : "r"(_m), "r"(_p) : "memory");  \
    if (!_d) {                                                                  \
        asm volatile("{\n .reg .pred P1;\n"                                     \
            "W_%=:\n"                                                           \
            " mbarrier.try_wait.parity.acquire.cta.shared::cta.b64 P1, [%0], %1, 0x989680;\n" \
            " @P1 bra.uni D_%=;\n bra.uni W_%=;\n"                              \
            "D_%=:\n}" :: "r"(_m), "r"(_p) : "memory");                         \
    } } while (0)

__device__ __forceinline__ void bulk_g2s(uint32_t dst, const void* src, uint32_t bytes, uint32_t mbar) {
    asm volatile(
        "cp.async.bulk.shared::cluster.global.mbarrier::complete_tx::bytes [%0], [%1], %2, [%3];"
        :: "r"(dst), "l"(src), "r"(bytes), "r"(mbar) : "memory");
}
#define CP_ASYNC16(sa, gp) \
    asm volatile("cp.async.ca.shared.global [%0], [%1], 16;" :: "r"(sa), "l"(gp) : "memory")
#define CP_ASYNC4(sa, gp) \
    asm volatile("cp.async.ca.shared.global [%0], [%1], 4;" :: "r"(sa), "l"(gp) : "memory")
#define CP_COMMIT() asm volatile("cp.async.commit_group;" ::: "memory")
#define CP_WAIT(n)  asm volatile("cp.async.wait_group %0;" :: "n"(n) : "memory")

__device__ __forceinline__ void mma_f16(float& c0, float& c1, float& c2, float& c3,
                                        uint32_t a0, uint32_t a1, uint32_t a2, uint32_t a3,
                                        uint32_t b0, uint32_t b1) {
    asm volatile(
        "mma.sync.aligned.m16n8k16.row.col.f32.f16.f16.f32 "
        "{%0,%1,%2,%3}, {%4,%5,%6,%7}, {%8,%9}, {%0,%1,%2,%3};"
        : "+f"(c0), "+f"(c1), "+f"(c2), "+f"(c3)
        : "r"(a0), "r"(a1), "r"(a2), "r"(a3), "r"(b0), "r"(b1));
}
#define LDS128(r0, r1, r2, r3, a) \
    asm volatile("ld.shared.v4.b32 {%0,%1,%2,%3}, [%4];" : "=r"(r0), "=r"(r1), "=r"(r2), "=r"(r3) : "r"(a))
#define LDS64(r0, r1, a) \
    asm volatile("ld.shared.v2.b32 {%0,%1}, [%2];" : "=r"(r0), "=r"(r1) : "r"(a))
#define STS128(a, r0, r1, r2, r3) \
    asm volatile("st.shared.v4.b32 [%0], {%1,%2,%3,%4};" :: "r"(a), "r"(r0), "r"(r1), "r"(r2), "r"(r3) : "memory")

// ---------------------------------------------------------------------------
// Routing core (warp-wide), identical semantics to validated R1/R4/R6/R7/R9.
// ---------------------------------------------------------------------------
__device__ __forceinline__ void route_core(const float s[8], const float ch[8],
                                           int lane, int t, float* out,
                                           bool do_margin, float* margin_e, float* margin_g)
{
    const unsigned FULL = 0xffffffffu;
    float m1 = -FLT_MAX, m2 = -FLT_MAX;
    #pragma unroll
    for (int j = 0; j < 8; j++) {
        float v = ch[j];
        if (v > m1) { m2 = m1; m1 = v; }
        else if (v > m2) { m2 = v; }
    }
    #pragma unroll
    for (int off = 1; off < 4; off <<= 1) {
        float om1 = __shfl_xor_sync(FULL, m1, off);
        float om2 = __shfl_xor_sync(FULL, m2, off);
        if (om1 > m1) { m2 = fmaxf(m1, om2); m1 = om1; }
        else          { m2 = fmaxf(m2, om1); }
    }
    float gs = m1 + m2;
    float gsv[8];
    #pragma unroll
    for (int gg = 0; gg < 8; gg++) gsv[gg] = __shfl_sync(FULL, gs, gg * 4);

    unsigned gmask = 0;
    float bv4 = -FLT_MAX;
    #pragma unroll
    for (int r = 0; r < TOPKG; r++) {
        float bv = -FLT_MAX; int bi = 0;
        #pragma unroll
        for (int gg = 0; gg < 8; gg++) {
            bool used = (gmask >> gg) & 1u;
            if (!used && gsv[gg] > bv) { bv = gsv[gg]; bi = gg; }
        }
        gmask |= (1u << bi);
        bv4 = bv;
    }
    if (do_margin) {
        float g5 = -FLT_MAX;
        #pragma unroll
        for (int gg = 0; gg < 8; gg++)
            if (!((gmask >> gg) & 1u) && gsv[gg] > g5) g5 = gsv[gg];
        *margin_g = bv4 - g5;
    }

    float tmp[8];
    bool gon = (gmask >> (lane >> 2)) & 1u;
    #pragma unroll
    for (int j = 0; j < 8; j++) tmp[j] = gon ? ch[j] : 0.0f;

    int   idxs[TOPK];
    float wts[TOPK];
    float wsum = 0.0f;
    float prevv = FLT_MAX, mgap = FLT_MAX;
    const int NROUND = 9;
    #pragma unroll
    for (int r = 0; r < NROUND; r++) {
        float bv = -FLT_MAX; int bj = 0;
        #pragma unroll
        for (int j = 0; j < 8; j++)
            if (tmp[j] > bv) { bv = tmp[j]; bj = j; }
        int gi = lane * 8 + bj;
        #pragma unroll
        for (int off = 16; off > 0; off >>= 1) {
            float ov = __shfl_xor_sync(FULL, bv, off);
            int   oi = __shfl_xor_sync(FULL, gi, off);
            if (ov > bv || (ov == bv && oi < gi)) { bv = ov; gi = oi; }
        }
        if (r > 0) mgap = fminf(mgap, prevv - bv);
        prevv = bv;
        if (r < TOPK) {
            float myw = s[gi & 7];
            float wv = __shfl_sync(FULL, myw, gi >> 3);
            if ((gi >> 3) == lane) tmp[gi & 7] = -FLT_MAX;
            idxs[r] = gi;
            wts[r]  = wv;
            wsum   += wv;
        }
        if (!do_margin && r == TOPK - 1) break;
    }
    if (do_margin) *margin_e = mgap;

    if (lane == 0) {
        float denom = wsum + 1e-20f;
        #pragma unroll
        for (int r = 0; r < TOPK; r++) {
            out[(size_t)t * TOPK + r] = (float)idxs[r];
            out[(size_t)T_TOKENS * TOPK + (size_t)t * TOPK + r] =
                (wts[r] / denom) * 2.5f;
        }
    }
}

// ---------------------------------------------------------------------------
// split_b: w -> fp16 hi/lo B fragments, stage-contiguous.
// ---------------------------------------------------------------------------
__global__ __launch_bounds__(256) void split_b_kernel(const float* __restrict__ w) {
    if (blockIdx.x == 0 && threadIdx.x == 0) g_nflag = 0;
    int tile = blockIdx.x * 8 + (threadIdx.x >> 5);   // nt*128 + kt
    int lane = threadIdx.x & 31;
    int nt = tile >> 7;
    int kt = tile & 127;
    int ks = kt >> 1, kt2 = kt & 1;
    int g = lane >> 2, t = lane & 3;
    const float* base = w + (size_t)(nt * 8 + g) * HDIM + kt * 16;
    float2 u0 = *(const float2*)(base + 2 * t);
    float2 u1 = *(const float2*)(base + 2 * t + 8);
    uint32_t b0h, b0l, b1h, b1l;
    split2(u0.x, u0.y, b0h, b0l);
    split2(u1.x, u1.y, b1h, b1l);
    size_t o = (size_t)(((ks * 32 + nt) * 2 + kt2)) * 64 + lane * 2;
    g_Bh1[o] = b0h; g_Bh1[o + 1] = b1h;
    g_Bh2[o] = b0l; g_Bh2[o + 1] = b1l;
}

// ---------------------------------------------------------------------------
// GEMM: fused A-split (LDG->split->STS) + 3x fp16 mma.sync, BM=128 BN=256.
// Writes sigmoid scores to g_scores (routing is a separate high-occupancy
// kernel: route_core is shfl-latency-bound and needs deep warp occupancy,
// which the 1-CTA/SM GEMM cannot provide — measured in R9).
// ---------------------------------------------------------------------------
#define BSTAGES  4
#define OFF_B    32768
#define B_STG_SZ 32768
#define OFF_MBAR (OFF_B + BSTAGES * B_STG_SZ)    // 163840
#define SMEM_SZ  (OFF_MBAR + 64)
#define NITER    (HDIM / 32)   // 64

__device__ __forceinline__ void issue_b(uint32_t sb, int s, int ks) {
    uint32_t stg = sb + OFF_B + s * B_STG_SZ;
    uint32_t mb  = sb + OFF_MBAR + s * 8;
    MBAR_EXPECT_TX(mb, B_STG_SZ);
    bulk_g2s(stg,         g_Bh1 + (size_t)ks * 4096, 16384, mb);
    bulk_g2s(stg + 16384, g_Bh2 + (size_t)ks * 4096, 16384, mb);
}

__device__ __forceinline__ void lda(const float* __restrict__ x, int bm, int ks,
                                    int wid, int g, int t, float2 pr[8]) {
    #pragma unroll
    for (int b = 0; b < 2; b++) {
        int bi = wid * 2 + b;
        int mt = bi >> 1, kt2 = bi & 1;
        const float* p = x + (size_t)(bm + mt * 16 + g) * HDIM + ks * 32 + kt2 * 16 + 2 * t;
        pr[b * 4 + 0] = *(const float2*)(p);
        pr[b * 4 + 1] = *(const float2*)(p + 8 * HDIM);
        pr[b * 4 + 2] = *(const float2*)(p + 8);
        pr[b * 4 + 3] = *(const float2*)(p + 8 * HDIM + 8);
    }
}
__device__ __forceinline__ void sts_a(uint32_t abuf, int wid, int lane, const float2 pr[8]) {
    #pragma unroll
    for (int b = 0; b < 2; b++) {
        int bi = wid * 2 + b;
        uint32_t h[4], l[4];
        #pragma unroll
        for (int j = 0; j < 4; j++)
            split2(pr[b * 4 + j].x, pr[b * 4 + j].y, h[j], l[j]);
        uint32_t dst = abuf + (uint32_t)bi * 512 + lane * 16;
        STS128(dst,        h[0], h[1], h[2], h[3]);
        STS128(dst + 8192, l[0], l[1], l[2], l[3]);
    }
}

__global__ __launch_bounds__(256, 1) void gemm_mma_kernel(const float* __restrict__ x) {
    extern __shared__ __align__(1024) char smem[];
    const uint32_t sb = smem_u32(smem);
    const int tid  = threadIdx.x;
    const int wid  = tid >> 5;
    const int lane = tid & 31;
    const int g    = lane >> 2, t = lane & 3;
    const int wm   = wid >> 2;
    const int wn   = wid & 3;
    const int bm   = blockIdx.x * 128;

    if (tid == 0) {
        #pragma unroll
        for (int s = 0; s < BSTAGES; s++) MBAR_INIT(sb + OFF_MBAR + s * 8, 1);
    }
    __syncthreads();
    if (tid == 0) {
        #pragma unroll
        for (int s = 0; s < BSTAGES; s++) issue_b(sb, s, s);
    }

    float2 pr[8];
    lda(x, bm, 0, wid, g, t, pr);
    sts_a(sb, wid, lane, pr);
    __syncthreads();

    float acc[4][8][4];
    #pragma unroll
    for (int i = 0; i < 4; i++)
        #pragma unroll
        for (int j = 0; j < 8; j++)
            #pragma unroll
            for (int q = 0; q < 4; q++) acc[i][j][q] = 0.0f;

    int ph[BSTAGES] = {0, 0, 0, 0};

    for (int it = 0; it < NITER; it++) {
        const int sB = it & (BSTAGES - 1);
        const uint32_t stgA = sb + (uint32_t)(it & 1) * 16384;
        const uint32_t stgB = sb + OFF_B + sB * B_STG_SZ;

        if (it + 1 < NITER) lda(x, bm, it + 1, wid, g, t, pr);

        MBAR_WAIT(sb + OFF_MBAR + sB * 8, ph[sB]);
        ph[sB] ^= 1;

        #pragma unroll
        for (int kt2 = 0; kt2 < 2; kt2++) {
            uint32_t ah[4][4], al[4][4], bh[8][2], bl[8][2];
            #pragma unroll
            for (int mi = 0; mi < 4; mi++) {
                uint32_t off = (uint32_t)(((wm * 4 + mi) * 2 + kt2) * 512 + lane * 16);
                LDS128(ah[mi][0], ah[mi][1], ah[mi][2], ah[mi][3], stgA + off);
                LDS128(al[mi][0], al[mi][1], al[mi][2], al[mi][3], stgA + 8192 + off);
            }
            #pragma unroll
            for (int ni = 0; ni < 8; ni++) {
                uint32_t off = (uint32_t)(((wn * 8 + ni) * 2 + kt2) * 256 + lane * 8);
                LDS64(bh[ni][0], bh[ni][1], stgB + off);
                LDS64(bl[ni][0], bl[ni][1], stgB + 16384 + off);
            }
            #pragma unroll
            for (int mi = 0; mi < 4; mi++)
                #pragma unroll
                for (int ni = 0; ni < 8; ni++) {
                    float* c = acc[mi][ni];
                    mma_f16(c[0], c[1], c[2], c[3],
                            ah[mi][0], ah[mi][1], ah[mi][2], ah[mi][3],
                            bh[ni][0], bh[ni][1]);
                    mma_f16(c[0], c[1], c[2], c[3],
                            ah[mi][0], ah[mi][1], ah[mi][2], ah[mi][3],
                            bl[ni][0], bl[ni][1]);
                    mma_f16(c[0], c[1], c[2], c[3],
                            al[mi][0], al[mi][1], al[mi][2], al[mi][3],
                            bh[ni][0], bh[ni][1]);
                }
        }

        if (it + 1 < NITER)
            sts_a(sb + (uint32_t)((it + 1) & 1) * 16384, wid, lane, pr);
        __syncthreads();
        if (tid == 0 && it + BSTAGES < NITER)
            issue_b(sb, sB, it + BSTAGES);
    }

    // epilogue: sigmoid -> g_scores
    #pragma unroll
    for (int mi = 0; mi < 4; mi++) {
        int r0 = bm + (wm * 4 + mi) * 16 + g;
        #pragma unroll
        for (int ni = 0; ni < 8; ni++) {
            int cc = (wn * 8 + ni) * 8 + t * 2;
            float* c = acc[mi][ni];
            float2 lo = make_float2(1.0f / (1.0f + expf(-c[0])),
                                    1.0f / (1.0f + expf(-c[1])));
            float2 hi = make_float2(1.0f / (1.0f + expf(-c[2])),
                                    1.0f / (1.0f + expf(-c[3])));
            *(float2*)(g_scores + (size_t)r0 * NEXP + cc) = lo;
            *(float2*)(g_scores + (size_t)(r0 + 8) * NEXP + cc) = hi;
        }
    }
}

// ---------------------------------------------------------------------------
// Routing kernel: one warp per token (deep occupancy hides shfl latency).
// ---------------------------------------------------------------------------
__global__ __launch_bounds__(256) void route_kernel(
    const float* __restrict__ bias, float* __restrict__ out)
{
    const int warp = threadIdx.x >> 5;
    const int lane = threadIdx.x & 31;
    const int t = blockIdx.x * 8 + warp;

    const float* sp = g_scores + (size_t)t * NEXP + lane * 8;
    float s[8], ch[8];
    float4 v0 = *(const float4*)(sp);
    float4 v1 = *(const float4*)(sp + 4);
    s[0]=v0.x; s[1]=v0.y; s[2]=v0.z; s[3]=v0.w;
    s[4]=v1.x; s[5]=v1.y; s[6]=v1.z; s[7]=v1.w;
    const float* bp = bias + lane * 8;
    float4 b0 = *(const float4*)(bp);
    float4 b1 = *(const float4*)(bp + 4);
    ch[0]=s[0]+b0.x; ch[1]=s[1]+b0.y; ch[2]=s[2]+b0.z; ch[3]=s[3]+b0.w;
    ch[4]=s[4]+b1.x; ch[5]=s[5]+b1.y; ch[6]=s[6]+b1.z; ch[7]=s[7]+b1.w;

    float me, mg;
    route_core(s, ch, lane, t, out, true, &me, &mg);

    if (lane == 0 && (me < TAU_E || mg < TAU_G)) {
        int p = atomicAdd(&g_nflag, 1);
        g_flaglist[p] = t;
    }
}

// ---------------------------------------------------------------------------
// Fixup: recompute flagged tokens (batches of 8 per CTA) with sequential fp32
// FFMA in strictly ascending k. Double-buffered w chunks via cp.async.
// dyn smem: xs[8][2048] | ws[2][256*33] | sc[8][256] = 141,312 B
// ---------------------------------------------------------------------------
#define WCH (256 * 33)
#define FIX_SMEM ((FTOK * HDIM + 2 * WCH + FTOK * NEXP) * 4)

__global__ __launch_bounds__(256) void fixup_kernel(
    const float* __restrict__ x, const float* __restrict__ w,
    const float* __restrict__ bias, float* __restrict__ out)
{
    extern __shared__ float fsm[];
    float* xs = fsm;                       // FTOK*HDIM
    float* ws = fsm + FTOK * HDIM;         // 2*WCH
    float* sc = ws + 2 * WCH;              // FTOK*NEXP
    const uint32_t fb = smem_u32(fsm);
    const uint32_t ws_base = fb + (uint32_t)(FTOK * HDIM) * 4;
    const int tid = threadIdx.x;
    const int nf = g_nflag;

    for (int base = blockIdx.x * FTOK; base < nf; base += gridDim.x * FTOK) {
        const int ntk = (nf - base < FTOK) ? (nf - base) : FTOK;
        __syncthreads();

        // xs via 16B cp.async
        #pragma unroll
        for (int j = 0; j < FTOK; j++) {
            int tt = g_flaglist[base + (j < ntk ? j : 0)];
            const float* src = x + (size_t)tt * HDIM;
            for (int i = tid * 4; i < HDIM; i += 1024)
                CP_ASYNC16(fb + (uint32_t)(j * HDIM + i) * 4, src + i);
        }
        // w chunk 0 via 4B cp.async (padded stride 33)
        #pragma unroll
        for (int jj = 0; jj < 32; jj++) {
            int idx = tid + jj * 256;
            int er = idx >> 5, kk = idx & 31;
            CP_ASYNC4(ws_base + (uint32_t)(er * 33 + kk) * 4, w + (size_t)er * HDIM + kk);
        }
        CP_COMMIT();

        float acc[FTOK];
        #pragma unroll
        for (int j = 0; j < FTOK; j++) acc[j] = 0.0f;

        for (int kc = 0; kc < 64; kc++) {
            const int bufc = kc & 1;
            if (kc + 1 < 64) {
                const uint32_t wb = ws_base + (uint32_t)((kc + 1) & 1) * (WCH * 4);
                #pragma unroll
                for (int jj = 0; jj < 32; jj++) {
                    int idx = tid + jj * 256;
                    int er = idx >> 5, kk = idx & 31;
                    CP_ASYNC4(wb + (uint32_t)(er * 33 + kk) * 4,
                              w + (size_t)er * HDIM + (kc + 1) * 32 + kk);
                }
                CP_COMMIT();
                CP_WAIT(1);
            } else {
                CP_WAIT(0);
            }
            __syncthreads();
            const float* we = ws + bufc * WCH + tid * 33;
            #pragma unroll
            for (int k = 0; k < 32; k++) {
                float wv = we[k];
                #pragma unroll
                for (int j = 0; j < FTOK; j++)
                    acc[j] = fmaf(xs[j * HDIM + kc * 32 + k], wv, acc[j]);
            }
            __syncthreads();
        }
        #pragma unroll
        for (int j = 0; j < FTOK; j++)
            sc[j * NEXP + tid] = 1.0f / (1.0f + expf(-acc[j]));
        __syncthreads();

        const int wid = tid >> 5, lane = tid & 31;
        if (wid < ntk) {
            int tt = g_flaglist[base + wid];
            float s[8], ch[8];
            #pragma unroll
            for (int j = 0; j < 8; j++) {
                s[j]  = sc[wid * NEXP + lane * 8 + j];
                ch[j] = s[j] + bias[lane * 8 + j];
            }
            float me, mg;
            route_core(s, ch, lane, tt, out, false, &me, &mg);
        }
    }
}

// ---------------------------------------------------------------------------
extern "C" void kernel_launch(void* const* d_in, const int* in_sizes, int n_in,
                              void* d_out, int out_size)
{
    const float* x    = (const float*)d_in[0];   // [4,4096,2048]
    const float* w    = (const float*)d_in[1];   // [256,2048]
    const float* bias = (const float*)d_in[2];   // [256]
    float* out = (float*)d_out;

    cudaFuncSetAttribute(gemm_mma_kernel,
                         cudaFuncAttributeMaxDynamicSharedMemorySize, SMEM_SZ);
    cudaFuncSetAttribute(fixup_kernel,
                         cudaFuncAttributeMaxDynamicSharedMemorySize, FIX_SMEM);

    split_b_kernel<<<(NEXP / 8) * (HDIM / 16) / 8, 256>>>(w);
    gemm_mma_kernel<<<T_TOKENS / 128, 256, SMEM_SZ>>>(x);
    route_kernel<<<T_TOKENS / 8, 256>>>(bias, out);
    fixup_kernel<<<148, 256, FIX_SMEM>>>(x, w, bias, out);
}

// round 11
// speedup vs baseline: 2.1275x; 1.0237x over previous
#include <cuda_runtime.h>
#include <cuda_fp16.h>
#include <math.h>
#include <float.h>
#include <stdint.h>

#define T_TOKENS 16384
#define HDIM     2048
#define NEXP     256
#define TOPK     8
#define TOPKG    4

#define TAU_E 1e-5f
#define TAU_G 2e-5f
#define FTOK  4          // fixup tokens per CTA batch

// ---------------- static device scratch ----------------
__device__ float g_scores[(size_t)T_TOKENS * NEXP];         // 16 MB
// B fragments, stage-contiguous: [ks(64)][nt(32)][kt2(2)][64 u32]
__device__ __align__(16) uint32_t g_Bh1[64 * 32 * 2 * 64];  // 1 MB
__device__ __align__(16) uint32_t g_Bh2[64 * 32 * 2 * 64];  // 1 MB
__device__ int   g_nflag;
__device__ int   g_flaglist[T_TOKENS];

// ---------------- helpers ----------------
__device__ __forceinline__ uint32_t smem_u32(const void* p) {
    uint32_t a;
    asm("{ .reg .u64 t; cvta.to.shared.u64 t, %1; cvt.u32.u64 %0, t; }" : "=r"(a) : "l"(p));
    return a;
}
__device__ __forceinline__ uint32_t pack_h2(__half lo, __half hi) {
    return (uint32_t)__half_as_ushort(lo) | ((uint32_t)__half_as_ushort(hi) << 16);
}
__device__ __forceinline__ void split2(float p, float q, uint32_t& hi, uint32_t& lo) {
    __half hp = __float2half_rn(p);
    __half hq = __float2half_rn(q);
    __half rp = __float2half_rn(p - __half2float(hp));
    __half rq = __float2half_rn(q - __half2float(hq));
    hi = pack_h2(hp, hq);
    lo = pack_h2(rp, rq);
}
#define MBAR_INIT(a, n) \
    asm volatile("mbarrier.init.shared.b64 [%0], %1;" :: "r"(a), "r"((uint32_t)(n)) : "memory")
#define MBAR_EXPECT_TX(a, b) \
    asm volatile("mbarrier.arrive.expect_tx.shared.b64 _, [%0], %1;" :: "r"(a), "r"((uint32_t)(b)) : "memory")
#define MBAR_WAIT(a, ph) do {                                                   \
    uint32_t _m = (a); uint32_t _p = (ph); uint32_t _d;                         \
    asm volatile("{\n .reg .pred p;\n"                                          \
        " mbarrier.try_wait.parity.acquire.cta.shared::cta.b64 p, [%1], %2;\n"  \
        " selp.b32 %0, 1, 0, p;\n}" : "=r"(_d) : "r"(_m), "r"(_p) : "memory");  \
    if (!_d) {                                                                  \
        asm volatile("{\n .reg .pred P1;\n"                                     \
            "W_%=:\n"                                                           \
            " mbarrier.try_wait.parity.acquire.cta.shared::cta.b64 P1, [%0], %1, 0x989680;\n" \
            " @P1 bra.uni D_%=;\n bra.uni W_%=;\n"                              \
            "D_%=:\n}" :: "r"(_m), "r"(_p) : "memory");                         \
    } } while (0)

__device__ __forceinline__ void bulk_g2s(uint32_t dst, const void* src, uint32_t bytes, uint32_t mbar) {
    asm volatile(
        "cp.async.bulk.shared::cluster.global.mbarrier::complete_tx::bytes [%0], [%1], %2, [%3];"
        :: "r"(dst), "l"(src), "r"(bytes), "r"(mbar) : "memory");
}
#define CP_ASYNC16(sa, gp) \
    asm volatile("cp.async.ca.shared.global [%0], [%1], 16;" :: "r"(sa), "l"(gp) : "memory")
#define CP_COMMIT() asm volatile("cp.async.commit_group;" ::: "memory")
#define CP_WAIT(n)  asm volatile("cp.async.wait_group %0;" :: "n"(n) : "memory")

__device__ __forceinline__ void mma_f16(float& c0, float& c1, float& c2, float& c3,
                                        uint32_t a0, uint32_t a1, uint32_t a2, uint32_t a3,
                                        uint32_t b0, uint32_t b1) {
    asm volatile(
        "mma.sync.aligned.m16n8k16.row.col.f32.f16.f16.f32 "
        "{%0,%1,%2,%3}, {%4,%5,%6,%7}, {%8,%9}, {%0,%1,%2,%3};"
        : "+f"(c0), "+f"(c1), "+f"(c2), "+f"(c3)
        : "r"(a0), "r"(a1), "r"(a2), "r"(a3), "r"(b0), "r"(b1));
}
#define LDS128(r0, r1, r2, r3, a) \
    asm volatile("ld.shared.v4.b32 {%0,%1,%2,%3}, [%4];" : "=r"(r0), "=r"(r1), "=r"(r2), "=r"(r3) : "r"(a))
#define LDS64(r0, r1, a) \
    asm volatile("ld.shared.v2.b32 {%0,%1}, [%2];" : "=r"(r0), "=r"(r1) : "r"(a))
#define STS128(a, r0, r1, r2, r3) \
    asm volatile("st.shared.v4.b32 [%0], {%1,%2,%3,%4};" :: "r"(a), "r"(r0), "r"(r1), "r"(r2), "r"(r3) : "memory")

// ---------------------------------------------------------------------------
// Routing core (warp-wide), identical semantics to validated R1/R4/R6/R7/R9.
// ---------------------------------------------------------------------------
__device__ __forceinline__ void route_core(const float s[8], const float ch[8],
                                           int lane, int t, float* out,
                                           bool do_margin, float* margin_e, float* margin_g)
{
    const unsigned FULL = 0xffffffffu;
    float m1 = -FLT_MAX, m2 = -FLT_MAX;
    #pragma unroll
    for (int j = 0; j < 8; j++) {
        float v = ch[j];
        if (v > m1) { m2 = m1; m1 = v; }
        else if (v > m2) { m2 = v; }
    }
    #pragma unroll
    for (int off = 1; off < 4; off <<= 1) {
        float om1 = __shfl_xor_sync(FULL, m1, off);
        float om2 = __shfl_xor_sync(FULL, m2, off);
        if (om1 > m1) { m2 = fmaxf(m1, om2); m1 = om1; }
        else          { m2 = fmaxf(m2, om1); }
    }
    float gs = m1 + m2;
    float gsv[8];
    #pragma unroll
    for (int gg = 0; gg < 8; gg++) gsv[gg] = __shfl_sync(FULL, gs, gg * 4);

    unsigned gmask = 0;
    float bv4 = -FLT_MAX;
    #pragma unroll
    for (int r = 0; r < TOPKG; r++) {
        float bv = -FLT_MAX; int bi = 0;
        #pragma unroll
        for (int gg = 0; gg < 8; gg++) {
            bool used = (gmask >> gg) & 1u;
            if (!used && gsv[gg] > bv) { bv = gsv[gg]; bi = gg; }
        }
        gmask |= (1u << bi);
        bv4 = bv;
    }
    if (do_margin) {
        float g5 = -FLT_MAX;
        #pragma unroll
        for (int gg = 0; gg < 8; gg++)
            if (!((gmask >> gg) & 1u) && gsv[gg] > g5) g5 = gsv[gg];
        *margin_g = bv4 - g5;
    }

    float tmp[8];
    bool gon = (gmask >> (lane >> 2)) & 1u;
    #pragma unroll
    for (int j = 0; j < 8; j++) tmp[j] = gon ? ch[j] : 0.0f;

    int   idxs[TOPK];
    float wts[TOPK];
    float wsum = 0.0f;
    float prevv = FLT_MAX, mgap = FLT_MAX;
    const int NROUND = 9;
    #pragma unroll
    for (int r = 0; r < NROUND; r++) {
        float bv = -FLT_MAX; int bj = 0;
        #pragma unroll
        for (int j = 0; j < 8; j++)
            if (tmp[j] > bv) { bv = tmp[j]; bj = j; }
        int gi = lane * 8 + bj;
        #pragma unroll
        for (int off = 16; off > 0; off >>= 1) {
            float ov = __shfl_xor_sync(FULL, bv, off);
            int   oi = __shfl_xor_sync(FULL, gi, off);
            if (ov > bv || (ov == bv && oi < gi)) { bv = ov; gi = oi; }
        }
        if (r > 0) mgap = fminf(mgap, prevv - bv);
        prevv = bv;
        if (r < TOPK) {
            float myw = s[gi & 7];
            float wv = __shfl_sync(FULL, myw, gi >> 3);
            if ((gi >> 3) == lane) tmp[gi & 7] = -FLT_MAX;
            idxs[r] = gi;
            wts[r]  = wv;
            wsum   += wv;
        }
        if (!do_margin && r == TOPK - 1) break;
    }
    if (do_margin) *margin_e = mgap;

    if (lane == 0) {
        float denom = wsum + 1e-20f;
        #pragma unroll
        for (int r = 0; r < TOPK; r++) {
            out[(size_t)t * TOPK + r] = (float)idxs[r];
            out[(size_t)T_TOKENS * TOPK + (size_t)t * TOPK + r] =
                (wts[r] / denom) * 2.5f;
        }
    }
}

// ---------------------------------------------------------------------------
// split_b: w -> fp16 hi/lo B fragments, stage-contiguous.
// ---------------------------------------------------------------------------
__global__ __launch_bounds__(256) void split_b_kernel(const float* __restrict__ w) {
    if (blockIdx.x == 0 && threadIdx.x == 0) g_nflag = 0;
    int tile = blockIdx.x * 8 + (threadIdx.x >> 5);   // nt*128 + kt
    int lane = threadIdx.x & 31;
    int nt = tile >> 7;
    int kt = tile & 127;
    int ks = kt >> 1, kt2 = kt & 1;
    int g = lane >> 2, t = lane & 3;
    const float* base = w + (size_t)(nt * 8 + g) * HDIM + kt * 16;
    float2 u0 = *(const float2*)(base + 2 * t);
    float2 u1 = *(const float2*)(base + 2 * t + 8);
    uint32_t b0h, b0l, b1h, b1l;
    split2(u0.x, u0.y, b0h, b0l);
    split2(u1.x, u1.y, b1h, b1l);
    size_t o = (size_t)(((ks * 32 + nt) * 2 + kt2)) * 64 + lane * 2;
    g_Bh1[o] = b0h; g_Bh1[o + 1] = b1h;
    g_Bh2[o] = b0l; g_Bh2[o + 1] = b1l;
}

// ---------------------------------------------------------------------------
// GEMM: fused A-split (LDG->split->STS) + 3x fp16 mma.sync, BM=128 BN=256.
// ---------------------------------------------------------------------------
#define BSTAGES  4
#define OFF_B    32768
#define B_STG_SZ 32768
#define OFF_MBAR (OFF_B + BSTAGES * B_STG_SZ)    // 163840
#define SMEM_SZ  (OFF_MBAR + 64)
#define NITER    (HDIM / 32)   // 64

__device__ __forceinline__ void issue_b(uint32_t sb, int s, int ks) {
    uint32_t stg = sb + OFF_B + s * B_STG_SZ;
    uint32_t mb  = sb + OFF_MBAR + s * 8;
    MBAR_EXPECT_TX(mb, B_STG_SZ);
    bulk_g2s(stg,         g_Bh1 + (size_t)ks * 4096, 16384, mb);
    bulk_g2s(stg + 16384, g_Bh2 + (size_t)ks * 4096, 16384, mb);
}

__device__ __forceinline__ void lda(const float* __restrict__ x, int bm, int ks,
                                    int wid, int g, int t, float2 pr[8]) {
    #pragma unroll
    for (int b = 0; b < 2; b++) {
        int bi = wid * 2 + b;
        int mt = bi >> 1, kt2 = bi & 1;
        const float* p = x + (size_t)(bm + mt * 16 + g) * HDIM + ks * 32 + kt2 * 16 + 2 * t;
        pr[b * 4 + 0] = *(const float2*)(p);
        pr[b * 4 + 1] = *(const float2*)(p + 8 * HDIM);
        pr[b * 4 + 2] = *(const float2*)(p + 8);
        pr[b * 4 + 3] = *(const float2*)(p + 8 * HDIM + 8);
    }
}
__device__ __forceinline__ void sts_a(uint32_t abuf, int wid, int lane, const float2 pr[8]) {
    #pragma unroll
    for (int b = 0; b < 2; b++) {
        int bi = wid * 2 + b;
        uint32_t h[4], l[4];
        #pragma unroll
        for (int j = 0; j < 4; j++)
            split2(pr[b * 4 + j].x, pr[b * 4 + j].y, h[j], l[j]);
        uint32_t dst = abuf + (uint32_t)bi * 512 + lane * 16;
        STS128(dst,        h[0], h[1], h[2], h[3]);
        STS128(dst + 8192, l[0], l[1], l[2], l[3]);
    }
}

__global__ __launch_bounds__(256, 1) void gemm_mma_kernel(const float* __restrict__ x) {
    extern __shared__ __align__(1024) char smem[];
    const uint32_t sb = smem_u32(smem);
    const int tid  = threadIdx.x;
    const int wid  = tid >> 5;
    const int lane = tid & 31;
    const int g    = lane >> 2, t = lane & 3;
    const int wm   = wid >> 2;
    const int wn   = wid & 3;
    const int bm   = blockIdx.x * 128;

    if (tid == 0) {
        #pragma unroll
        for (int s = 0; s < BSTAGES; s++) MBAR_INIT(sb + OFF_MBAR + s * 8, 1);
    }
    __syncthreads();
    if (tid == 0) {
        #pragma unroll
        for (int s = 0; s < BSTAGES; s++) issue_b(sb, s, s);
    }

    float2 pr[8];
    lda(x, bm, 0, wid, g, t, pr);
    sts_a(sb, wid, lane, pr);
    __syncthreads();

    float acc[4][8][4];
    #pragma unroll
    for (int i = 0; i < 4; i++)
        #pragma unroll
        for (int j = 0; j < 8; j++)
            #pragma unroll
            for (int q = 0; q < 4; q++) acc[i][j][q] = 0.0f;

    int ph[BSTAGES] = {0, 0, 0, 0};

    for (int it = 0; it < NITER; it++) {
        const int sB = it & (BSTAGES - 1);
        const uint32_t stgA = sb + (uint32_t)(it & 1) * 16384;
        const uint32_t stgB = sb + OFF_B + sB * B_STG_SZ;

        if (it + 1 < NITER) lda(x, bm, it + 1, wid, g, t, pr);

        MBAR_WAIT(sb + OFF_MBAR + sB * 8, ph[sB]);
        ph[sB] ^= 1;

        #pragma unroll
        for (int kt2 = 0; kt2 < 2; kt2++) {
            uint32_t ah[4][4], al[4][4], bh[8][2], bl[8][2];
            #pragma unroll
            for (int mi = 0; mi < 4; mi++) {
                uint32_t off = (uint32_t)(((wm * 4 + mi) * 2 + kt2) * 512 + lane * 16);
                LDS128(ah[mi][0], ah[mi][1], ah[mi][2], ah[mi][3], stgA + off);
                LDS128(al[mi][0], al[mi][1], al[mi][2], al[mi][3], stgA + 8192 + off);
            }
            #pragma unroll
            for (int ni = 0; ni < 8; ni++) {
                uint32_t off = (uint32_t)(((wn * 8 + ni) * 2 + kt2) * 256 + lane * 8);
                LDS64(bh[ni][0], bh[ni][1], stgB + off);
                LDS64(bl[ni][0], bl[ni][1], stgB + 16384 + off);
            }
            #pragma unroll
            for (int mi = 0; mi < 4; mi++)
                #pragma unroll
                for (int ni = 0; ni < 8; ni++) {
                    float* c = acc[mi][ni];
                    mma_f16(c[0], c[1], c[2], c[3],
                            ah[mi][0], ah[mi][1], ah[mi][2], ah[mi][3],
                            bh[ni][0], bh[ni][1]);
                    mma_f16(c[0], c[1], c[2], c[3],
                            ah[mi][0], ah[mi][1], ah[mi][2], ah[mi][3],
                            bl[ni][0], bl[ni][1]);
                    mma_f16(c[0], c[1], c[2], c[3],
                            al[mi][0], al[mi][1], al[mi][2], al[mi][3],
                            bh[ni][0], bh[ni][1]);
                }
        }

        if (it + 1 < NITER)
            sts_a(sb + (uint32_t)((it + 1) & 1) * 16384, wid, lane, pr);
        __syncthreads();
        if (tid == 0 && it + BSTAGES < NITER)
            issue_b(sb, sB, it + BSTAGES);
    }

    // epilogue: sigmoid -> g_scores
    #pragma unroll
    for (int mi = 0; mi < 4; mi++) {
        int r0 = bm + (wm * 4 + mi) * 16 + g;
        #pragma unroll
        for (int ni = 0; ni < 8; ni++) {
            int cc = (wn * 8 + ni) * 8 + t * 2;
            float* c = acc[mi][ni];
            float2 lo = make_float2(1.0f / (1.0f + expf(-c[0])),
                                    1.0f / (1.0f + expf(-c[1])));
            float2 hi = make_float2(1.0f / (1.0f + expf(-c[2])),
                                    1.0f / (1.0f + expf(-c[3])));
            *(float2*)(g_scores + (size_t)r0 * NEXP + cc) = lo;
            *(float2*)(g_scores + (size_t)(r0 + 8) * NEXP + cc) = hi;
        }
    }
}

// ---------------------------------------------------------------------------
// Routing kernel: one warp per token (deep occupancy hides shfl latency).
// ---------------------------------------------------------------------------
__global__ __launch_bounds__(256) void route_kernel(
    const float* __restrict__ bias, float* __restrict__ out)
{
    const int warp = threadIdx.x >> 5;
    const int lane = threadIdx.x & 31;
    const int t = blockIdx.x * 8 + warp;

    const float* sp = g_scores + (size_t)t * NEXP + lane * 8;
    float s[8], ch[8];
    float4 v0 = *(const float4*)(sp);
    float4 v1 = *(const float4*)(sp + 4);
    s[0]=v0.x; s[1]=v0.y; s[2]=v0.z; s[3]=v0.w;
    s[4]=v1.x; s[5]=v1.y; s[6]=v1.z; s[7]=v1.w;
    const float* bp = bias + lane * 8;
    float4 b0 = *(const float4*)(bp);
    float4 b1 = *(const float4*)(bp + 4);
    ch[0]=s[0]+b0.x; ch[1]=s[1]+b0.y; ch[2]=s[2]+b0.z; ch[3]=s[3]+b0.w;
    ch[4]=s[4]+b1.x; ch[5]=s[5]+b1.y; ch[6]=s[6]+b1.z; ch[7]=s[7]+b1.w;

    float me, mg;
    route_core(s, ch, lane, t, out, true, &me, &mg);

    if (lane == 0 && (me < TAU_E || mg < TAU_G)) {
        int p = atomicAdd(&g_nflag, 1);
        g_flaglist[p] = t;
    }
}

// ---------------------------------------------------------------------------
// Fixup: recompute flagged tokens (batches of FTOK=4 per CTA) with sequential
// fp32 FFMA in strictly ascending k (bitwise-identical chain to R7/R9/R10).
// w chunks staged in smem via 16B cp.async with a 16B-block XOR swizzle
// (c4 ^= er&7): cp.async-legal, and limits main-loop LDS conflict to 4-way.
// dyn smem: xs[4][2048] | ws[2][256*32] | sc[4][256] = 32K + 64K + 4K = 100K
// ---------------------------------------------------------------------------
#define WCHUNK (256 * 32)
#define FIX_SMEM ((FTOK * HDIM + 2 * WCHUNK + FTOK * NEXP) * 4)

__global__ __launch_bounds__(256) void fixup_kernel(
    const float* __restrict__ x, const float* __restrict__ w,
    const float* __restrict__ bias, float* __restrict__ out)
{
    extern __shared__ float fsm[];
    float* xs = fsm;                       // FTOK*HDIM
    float* ws = fsm + FTOK * HDIM;         // 2*WCHUNK
    float* sc = ws + 2 * WCHUNK;           // FTOK*NEXP
    const uint32_t fb = smem_u32(fsm);
    const uint32_t ws_base = fb + (uint32_t)(FTOK * HDIM) * 4;
    const int tid = threadIdx.x;
    const int nf = g_nflag;

    for (int base = blockIdx.x * FTOK; base < nf; base += gridDim.x * FTOK) {
        const int ntk = (nf - base < FTOK) ? (nf - base) : FTOK;
        __syncthreads();

        // xs via 16B cp.async
        #pragma unroll
        for (int j = 0; j < FTOK; j++) {
            int tt = g_flaglist[base + (j < ntk ? j : 0)];
            const float* src = x + (size_t)tt * HDIM;
            #pragma unroll
            for (int i = tid * 4; i < HDIM; i += 1024)
                CP_ASYNC16(fb + (uint32_t)(j * HDIM + i) * 4, src + i);
        }
        // w chunk 0: 16B copies, block-XOR swizzled dst, coalesced src
        #pragma unroll
        for (int i = 0; i < 8; i++) {
            int idx = tid + 256 * i;
            int er = idx >> 3, c4 = idx & 7;
            uint32_t dst = ws_base + (uint32_t)(er * 128 + ((c4 ^ (er & 7)) * 16));
            CP_ASYNC16(dst, w + (size_t)er * HDIM + c4 * 4);
        }
        CP_COMMIT();

        float acc[FTOK];
        #pragma unroll
        for (int j = 0; j < FTOK; j++) acc[j] = 0.0f;

        const int er = tid;
        for (int kc = 0; kc < 64; kc++) {
            const int bufc = kc & 1;
            if (kc + 1 < 64) {
                const uint32_t wb = ws_base + (uint32_t)(((kc + 1) & 1)) * (WCHUNK * 4);
                #pragma unroll
                for (int i = 0; i < 8; i++) {
                    int idx = tid + 256 * i;
                    int e2 = idx >> 3, c4 = idx & 7;
                    uint32_t dst = wb + (uint32_t)(e2 * 128 + ((c4 ^ (e2 & 7)) * 16));
                    CP_ASYNC16(dst, w + (size_t)e2 * HDIM + (kc + 1) * 32 + c4 * 4);
                }
                CP_COMMIT();
                CP_WAIT(1);
            } else {
                CP_WAIT(0);
            }
            __syncthreads();
            const float* wbuf = ws + bufc * WCHUNK;
            #pragma unroll
            for (int k = 0; k < 32; k++) {
                float wv = wbuf[er * 32 + (((k >> 2) ^ (er & 7)) << 2) + (k & 3)];
                #pragma unroll
                for (int j = 0; j < FTOK; j++)
                    acc[j] = fmaf(xs[j * HDIM + kc * 32 + k], wv, acc[j]);
            }
            __syncthreads();
        }
        #pragma unroll
        for (int j = 0; j < FTOK; j++)
            sc[j * NEXP + tid] = 1.0f / (1.0f + expf(-acc[j]));
        __syncthreads();

        const int wid = tid >> 5, lane = tid & 31;
        if (wid < ntk) {
            int tt = g_flaglist[base + wid];
            float s[8], ch[8];
            #pragma unroll
            for (int j = 0; j < 8; j++) {
                s[j]  = sc[wid * NEXP + lane * 8 + j];
                ch[j] = s[j] + bias[lane * 8 + j];
            }
            float me, mg;
            route_core(s, ch, lane, tt, out, false, &me, &mg);
        }
    }
}

// ---------------------------------------------------------------------------
extern "C" void kernel_launch(void* const* d_in, const int* in_sizes, int n_in,
                              void* d_out, int out_size)
{
    const float* x    = (const float*)d_in[0];   // [4,4096,2048]
    const float* w    = (const float*)d_in[1];   // [256,2048]
    const float* bias = (const float*)d_in[2];   // [256]
    float* out = (float*)d_out;

    cudaFuncSetAttribute(gemm_mma_kernel,
                         cudaFuncAttributeMaxDynamicSharedMemorySize, SMEM_SZ);
    cudaFuncSetAttribute(fixup_kernel,
                         cudaFuncAttributeMaxDynamicSharedMemorySize, FIX_SMEM);

    split_b_kernel<<<(NEXP / 8) * (HDIM / 16) / 8, 256>>>(w);
    gemm_mma_kernel<<<T_TOKENS / 128, 256, SMEM_SZ>>>(x);
    route_kernel<<<T_TOKENS / 8, 256>>>(bias, out);
    fixup_kernel<<<512, 256, FIX_SMEM>>>(x, w, bias, out);
}